// round 1
// baseline (speedup 1.0000x reference)
#include <cuda_runtime.h>
#include <cuda_bf16.h>
#include <math.h>
#include <stdint.h>

// ---------------------------------------------------------------------------
// GroupedQueryAttention  (B=2, T=2048, DIM=2048, H=16, KVH=4, D=128, causal+RoPE)
//
// Pipeline:
//   1) rope_table_kernel : cos/sin tables (double-accurate), [T, 64]
//   2) gemm_nt_kernel    : q = x @ wq^T            [4096, 2048]
//   3) gemm_nt_kernel    : k = x @ wk^T + bk       [4096,  512]
//   4) gemm_nt_kernel    : v = x @ wv^T + bv       [4096,  512]
//   5) rope_kernel       : in-place RoPE on q and k
//   6) flash_kernel      : causal flash attention  -> attn [4096, 2048]
//   7) gemm_nt_kernel    : out = attn @ wo^T + bo  [4096, 2048]
// ---------------------------------------------------------------------------

#define DIM      2048
#define HEAD_DIM 128
#define N_HEAD   16
#define N_KVH    4
#define SEQ_T    2048
#define BATCH    2
#define M_ROWS   (BATCH * SEQ_T)          // 4096

// ------------------------------ scratch -----------------------------------
__device__ float g_q   [(size_t)M_ROWS * DIM];            // [B*T, 16*128]
__device__ float g_k   [(size_t)M_ROWS * N_KVH * HEAD_DIM];
__device__ float g_v   [(size_t)M_ROWS * N_KVH * HEAD_DIM];
__device__ float g_attn[(size_t)M_ROWS * DIM];
__device__ float g_cos [SEQ_T * 64];
__device__ float g_sin [SEQ_T * 64];

// ------------------------- RoPE tables (double) ----------------------------
__global__ void rope_table_kernel(float* ctab, float* stab) {
    int idx = blockIdx.x * blockDim.x + threadIdx.x;   // T*64 threads
    int t = idx >> 6;
    int j = idx & 63;
    double theta = exp(-((double)(2 * j) / 128.0) * log(10000.0));
    double ang = (double)t * theta;
    ctab[idx] = (float)cos(ang);
    stab[idx] = (float)sin(ang);
}

// --------------------------- RoPE apply (in place) --------------------------
// X layout: [B, T, H*128]; rotate pair (d, d+64) within each head.
__global__ void rope_kernel(float* __restrict__ X,
                            const float* __restrict__ ctab,
                            const float* __restrict__ stab,
                            int H) {
    int idx = blockIdx.x * blockDim.x + threadIdx.x;   // B*T*H*64 threads
    int j = idx & 63;
    int r = idx >> 6;
    int h = r % H;
    int r2 = r / H;
    int t = r2 % SEQ_T;
    int b = r2 / SEQ_T;
    float* p = X + ((size_t)(b * SEQ_T + t) * H + h) * HEAD_DIM;
    float c = ctab[t * 64 + j];
    float s = stab[t * 64 + j];
    float x1 = p[j];
    float x2 = p[j + 64];
    p[j]      = x1 * c - x2 * s;
    p[j + 64] = x2 * c + x1 * s;
}

// ------------------------------ GEMM (NT) -----------------------------------
// C[M,N] = A[M,K] @ W[N,K]^T (+ bias[n]).  M,N multiples of 128, K of 8.
// 128x128 tile, TK=8, 256 threads, 8x8 per-thread register block.
__global__ void __launch_bounds__(256)
gemm_nt_kernel(const float* __restrict__ A, const float* __restrict__ W,
               const float* __restrict__ bias, float* __restrict__ C,
               int M, int N, int K) {
    __shared__ float As[8][128];
    __shared__ float Bs[8][128];

    int tid = threadIdx.x;
    int tx = tid & 15;
    int ty = tid >> 4;
    int bx = blockIdx.x;   // N tile
    int by = blockIdx.y;   // M tile

    const float* Ablk = A + (size_t)by * 128 * K;
    const float* Wblk = W + (size_t)bx * 128 * K;

    int lr = tid >> 1;          // 0..127: row within tile
    int lc = (tid & 1) * 4;     // 0 or 4: k offset

    float acc[8][8];
#pragma unroll
    for (int i = 0; i < 8; i++)
#pragma unroll
        for (int j = 0; j < 8; j++) acc[i][j] = 0.f;

    for (int kt = 0; kt < K; kt += 8) {
        float4 av = *(const float4*)(Ablk + (size_t)lr * K + kt + lc);
        float4 wv = *(const float4*)(Wblk + (size_t)lr * K + kt + lc);
        __syncthreads();
        As[lc + 0][lr] = av.x; As[lc + 1][lr] = av.y;
        As[lc + 2][lr] = av.z; As[lc + 3][lr] = av.w;
        Bs[lc + 0][lr] = wv.x; Bs[lc + 1][lr] = wv.y;
        Bs[lc + 2][lr] = wv.z; Bs[lc + 3][lr] = wv.w;
        __syncthreads();
#pragma unroll
        for (int k = 0; k < 8; k++) {
            float a[8], b[8];
            float4 t0 = *(const float4*)&As[k][ty * 4];
            float4 t1 = *(const float4*)&As[k][64 + ty * 4];
            float4 u0 = *(const float4*)&Bs[k][tx * 4];
            float4 u1 = *(const float4*)&Bs[k][64 + tx * 4];
            a[0]=t0.x; a[1]=t0.y; a[2]=t0.z; a[3]=t0.w;
            a[4]=t1.x; a[5]=t1.y; a[6]=t1.z; a[7]=t1.w;
            b[0]=u0.x; b[1]=u0.y; b[2]=u0.z; b[3]=u0.w;
            b[4]=u1.x; b[5]=u1.y; b[6]=u1.z; b[7]=u1.w;
#pragma unroll
            for (int i = 0; i < 8; i++)
#pragma unroll
                for (int j = 0; j < 8; j++)
                    acc[i][j] += a[i] * b[j];
        }
    }

    // bias (per output column)
    float bv0[8];
#pragma unroll
    for (int j = 0; j < 8; j++) {
        int col = bx * 128 + ((j < 4) ? (tx * 4 + j) : (64 + tx * 4 + j - 4));
        bv0[j] = bias ? bias[col] : 0.f;
    }

#pragma unroll
    for (int i = 0; i < 8; i++) {
        int row = by * 128 + ((i < 4) ? (ty * 4 + i) : (64 + ty * 4 + i - 4));
        float* Crow = C + (size_t)row * N + bx * 128;
        float4 v0, v1;
        v0.x = acc[i][0] + bv0[0]; v0.y = acc[i][1] + bv0[1];
        v0.z = acc[i][2] + bv0[2]; v0.w = acc[i][3] + bv0[3];
        v1.x = acc[i][4] + bv0[4]; v1.y = acc[i][5] + bv0[5];
        v1.z = acc[i][6] + bv0[6]; v1.w = acc[i][7] + bv0[7];
        *(float4*)(Crow + tx * 4)      = v0;
        *(float4*)(Crow + 64 + tx * 4) = v1;
    }
}

// ----------------------------- Flash attention ------------------------------
// Per block: one (b, h) and BM=64 query rows.  Iterate causal key tiles BN=64.
// Q layout [B*T, 16, 128]; K/V layout [B*T, 4, 128]; out -> g_attn [B*T, 16*128].
#define BM 64
#define BN 64
#define KSTR 132          // K smem row stride (floats) — bank-spread for S compute
#define PSTR 68           // P smem row stride (floats), 16B aligned

__global__ void __launch_bounds__(256, 2)
flash_kernel(const float* __restrict__ Q, const float* __restrict__ K,
             const float* __restrict__ V, float* __restrict__ O) {
    extern __shared__ float sm[];
    float* Qs = sm;                    // 64*128
    float* Ks = Qs + BM * HEAD_DIM;    // 64*132
    float* Vs = Ks + BN * KSTR;        // 64*128
    float* Ps = Ks;                    // overlay: P reuses K buffer

    int tid = threadIdx.x;
    int tx = tid & 15;
    int ty = tid >> 4;
    int qt = blockIdx.x;
    int h  = blockIdx.y;
    int b  = blockIdx.z;
    int kvh = h >> 2;                  // GQA: 4 query heads per kv head
    int q0 = qt * BM;

    const float scale = 0.08838834764831845f;   // 1/sqrt(128)

    int lrow = tid >> 2;               // 0..63
    int lc4  = tid & 3;                // 0..3

    // Load Q tile (pre-scaled)
    {
        const float* src = Q + ((size_t)(b * SEQ_T + q0 + lrow) * N_HEAD + h) * HEAD_DIM;
        float* dst = Qs + lrow * HEAD_DIM;
#pragma unroll
        for (int u = 0; u < 8; u++) {
            float4 v = *(const float4*)(src + (lc4 + 4 * u) * 4);
            v.x *= scale; v.y *= scale; v.z *= scale; v.w *= scale;
            *(float4*)(dst + (lc4 + 4 * u) * 4) = v;
        }
    }

    float m[4], l[4], o[4][8];
#pragma unroll
    for (int i = 0; i < 4; i++) {
        m[i] = -INFINITY; l[i] = 0.f;
#pragma unroll
        for (int u = 0; u < 8; u++) o[i][u] = 0.f;
    }

    int ktiles = qt + 1;
    for (int kt2 = 0; kt2 < ktiles; kt2++) {
        int k0 = kt2 * BN;
        __syncthreads();   // protect Qs (first iter) / Ps,Vs (prev iter) before overwrite
        // load K, V tiles
        {
            const float* ksrc = K + ((size_t)(b * SEQ_T + k0 + lrow) * N_KVH + kvh) * HEAD_DIM;
            const float* vsrc = V + ((size_t)(b * SEQ_T + k0 + lrow) * N_KVH + kvh) * HEAD_DIM;
            float* kdst = Ks + lrow * KSTR;
            float* vdst = Vs + lrow * HEAD_DIM;
#pragma unroll
            for (int u = 0; u < 8; u++) {
                *(float4*)(kdst + (lc4 + 4 * u) * 4) = *(const float4*)(ksrc + (lc4 + 4 * u) * 4);
                *(float4*)(vdst + (lc4 + 4 * u) * 4) = *(const float4*)(vsrc + (lc4 + 4 * u) * 4);
            }
        }
        __syncthreads();

        // S = Qs @ Ks^T : rows 4*ty+i, cols tx+16*j
        float s[4][4];
#pragma unroll
        for (int i = 0; i < 4; i++)
#pragma unroll
            for (int j = 0; j < 4; j++) s[i][j] = 0.f;

        for (int kk4 = 0; kk4 < 32; kk4++) {
            float4 qv[4], kv[4];
#pragma unroll
            for (int i = 0; i < 4; i++)
                qv[i] = *(const float4*)(Qs + (4 * ty + i) * HEAD_DIM + kk4 * 4);
#pragma unroll
            for (int j = 0; j < 4; j++)
                kv[j] = *(const float4*)(Ks + (tx + 16 * j) * KSTR + kk4 * 4);
#pragma unroll
            for (int i = 0; i < 4; i++)
#pragma unroll
                for (int j = 0; j < 4; j++)
                    s[i][j] += qv[i].x * kv[j].x + qv[i].y * kv[j].y
                             + qv[i].z * kv[j].z + qv[i].w * kv[j].w;
        }

        // causal mask (diagonal tile only)
        if (kt2 == qt) {
#pragma unroll
            for (int i = 0; i < 4; i++)
#pragma unroll
                for (int j = 0; j < 4; j++)
                    if (k0 + tx + 16 * j > q0 + 4 * ty + i) s[i][j] = -INFINITY;
        }

        // row max over this tile (per-thread then across 16 lanes)
        float rm[4];
#pragma unroll
        for (int i = 0; i < 4; i++) {
            rm[i] = fmaxf(fmaxf(s[i][0], s[i][1]), fmaxf(s[i][2], s[i][3]));
#pragma unroll
            for (int d = 1; d < 16; d <<= 1)
                rm[i] = fmaxf(rm[i], __shfl_xor_sync(0xffffffffu, rm[i], d));
        }

        float p[4][4], f[4], rs[4];
#pragma unroll
        for (int i = 0; i < 4; i++) {
            float mn = fmaxf(m[i], rm[i]);
            f[i] = __expf(m[i] - mn);
            m[i] = mn;
            rs[i] = 0.f;
#pragma unroll
            for (int j = 0; j < 4; j++) {
                p[i][j] = __expf(s[i][j] - mn);
                rs[i] += p[i][j];
            }
#pragma unroll
            for (int d = 1; d < 16; d <<= 1)
                rs[i] += __shfl_xor_sync(0xffffffffu, rs[i], d);
            l[i] = l[i] * f[i] + rs[i];
#pragma unroll
            for (int u = 0; u < 8; u++) o[i][u] *= f[i];
        }

        __syncthreads();   // all Ks reads done before P overwrites the buffer
#pragma unroll
        for (int i = 0; i < 4; i++)
#pragma unroll
            for (int j = 0; j < 4; j++)
                Ps[(4 * ty + i) * PSTR + tx + 16 * j] = p[i][j];
        __syncthreads();

        // O += P @ V
        for (int s4 = 0; s4 < 16; s4++) {
            float4 pv[4];
#pragma unroll
            for (int i = 0; i < 4; i++)
                pv[i] = *(const float4*)(Ps + (4 * ty + i) * PSTR + s4 * 4);
#pragma unroll
            for (int ss = 0; ss < 4; ss++) {
                float pe[4];
                pe[0] = (ss == 0) ? pv[0].x : (ss == 1) ? pv[0].y : (ss == 2) ? pv[0].z : pv[0].w;
                pe[1] = (ss == 0) ? pv[1].x : (ss == 1) ? pv[1].y : (ss == 2) ? pv[1].z : pv[1].w;
                pe[2] = (ss == 0) ? pv[2].x : (ss == 1) ? pv[2].y : (ss == 2) ? pv[2].z : pv[2].w;
                pe[3] = (ss == 0) ? pv[3].x : (ss == 1) ? pv[3].y : (ss == 2) ? pv[3].z : pv[3].w;
#pragma unroll
                for (int u = 0; u < 8; u++) {
                    float vv = Vs[(s4 * 4 + ss) * HEAD_DIM + tx + 16 * u];
#pragma unroll
                    for (int i = 0; i < 4; i++) o[i][u] += pe[i] * vv;
                }
            }
        }
    }

    // epilogue: normalize and write [B*T, 16*128]
#pragma unroll
    for (int i = 0; i < 4; i++) {
        float inv = 1.f / l[i];
        float* dst = O + ((size_t)(b * SEQ_T + q0 + 4 * ty + i) * N_HEAD + h) * HEAD_DIM;
#pragma unroll
        for (int u = 0; u < 8; u++)
            dst[tx + 16 * u] = o[i][u] * inv;
    }
}

// ------------------------------- launch ------------------------------------
extern "C" void kernel_launch(void* const* d_in, const int* in_sizes, int n_in,
                              void* d_out, int out_size) {
    const float* x  = (const float*)d_in[0];
    const float* wq = (const float*)d_in[1];
    const float* wk = (const float*)d_in[2];
    const float* bk = (const float*)d_in[3];
    const float* wv = (const float*)d_in[4];
    const float* bv = (const float*)d_in[5];
    const float* wo = (const float*)d_in[6];
    const float* bo = (const float*)d_in[7];
    float* out = (float*)d_out;

    float *qp, *kp, *vp, *ap, *ct, *st;
    cudaGetSymbolAddress((void**)&qp, g_q);
    cudaGetSymbolAddress((void**)&kp, g_k);
    cudaGetSymbolAddress((void**)&vp, g_v);
    cudaGetSymbolAddress((void**)&ap, g_attn);
    cudaGetSymbolAddress((void**)&ct, g_cos);
    cudaGetSymbolAddress((void**)&st, g_sin);

    // 1) RoPE tables
    rope_table_kernel<<<(SEQ_T * 64) / 256, 256>>>(ct, st);

    // 2-4) QKV projections
    gemm_nt_kernel<<<dim3(DIM / 128, M_ROWS / 128), 256>>>(x, wq, nullptr, qp,
                                                           M_ROWS, DIM, DIM);
    gemm_nt_kernel<<<dim3((N_KVH * HEAD_DIM) / 128, M_ROWS / 128), 256>>>(
        x, wk, bk, kp, M_ROWS, N_KVH * HEAD_DIM, DIM);
    gemm_nt_kernel<<<dim3((N_KVH * HEAD_DIM) / 128, M_ROWS / 128), 256>>>(
        x, wv, bv, vp, M_ROWS, N_KVH * HEAD_DIM, DIM);

    // 5) RoPE on q and k (in place)
    rope_kernel<<<((size_t)M_ROWS * N_HEAD * 64) / 256, 256>>>(qp, ct, st, N_HEAD);
    rope_kernel<<<((size_t)M_ROWS * N_KVH * 64) / 256, 256>>>(kp, ct, st, N_KVH);

    // 6) flash attention
    size_t smem = (size_t)(BM * HEAD_DIM + BN * KSTR + BN * HEAD_DIM) * sizeof(float);
    cudaFuncSetAttribute(flash_kernel, cudaFuncAttributeMaxDynamicSharedMemorySize,
                         (int)smem);
    flash_kernel<<<dim3(SEQ_T / BM, N_HEAD, BATCH), 256, smem>>>(qp, kp, vp, ap);

    // 7) output projection
    gemm_nt_kernel<<<dim3(DIM / 128, M_ROWS / 128), 256>>>(ap, wo, bo, out,
                                                           M_ROWS, DIM, DIM);
}

// round 2
// speedup vs baseline: 3.0974x; 3.0974x over previous
#include <cuda_runtime.h>
#include <cuda_bf16.h>
#include <math.h>
#include <stdint.h>

// ---------------------------------------------------------------------------
// GroupedQueryAttention — tf32 tensor-core version
//   B=2, T=2048, DIM=2048, H=16, KVH=4, D=128, causal + RoPE
// All matmuls on mma.sync.m16n8k8.tf32, fp32 accumulate; softmax/RoPE fp32.
// ---------------------------------------------------------------------------

#define DIM      2048
#define HEAD_DIM 128
#define N_HEAD   16
#define N_KVH    4
#define SEQ_T    2048
#define BATCH    2
#define M_ROWS   (BATCH * SEQ_T)          // 4096

// ------------------------------ scratch -----------------------------------
__device__ float g_q   [(size_t)M_ROWS * DIM];
__device__ float g_k   [(size_t)M_ROWS * N_KVH * HEAD_DIM];
__device__ float g_v   [(size_t)M_ROWS * N_KVH * HEAD_DIM];
__device__ float g_attn[(size_t)M_ROWS * DIM];
__device__ float g_cos [SEQ_T * 64];
__device__ float g_sin [SEQ_T * 64];

// ------------------------------ helpers ------------------------------------
__device__ __forceinline__ uint32_t f2tf(float f) {
    uint32_t u;
    asm("cvt.rna.tf32.f32 %0, %1;" : "=r"(u) : "f"(f));
    return u;
}

__device__ __forceinline__ void mma_tf32(float c[4], const uint32_t a[4],
                                         const uint32_t b[2]) {
    asm("mma.sync.aligned.m16n8k8.row.col.f32.tf32.tf32.f32 "
        "{%0,%1,%2,%3},{%4,%5,%6,%7},{%8,%9},{%0,%1,%2,%3};"
        : "+f"(c[0]), "+f"(c[1]), "+f"(c[2]), "+f"(c[3])
        : "r"(a[0]), "r"(a[1]), "r"(a[2]), "r"(a[3]), "r"(b[0]), "r"(b[1]));
}

// ------------------------- RoPE tables (double) ----------------------------
__global__ void rope_table_kernel(float* ctab, float* stab) {
    int idx = blockIdx.x * blockDim.x + threadIdx.x;
    int t = idx >> 6;
    int j = idx & 63;
    double theta = exp(-((double)(2 * j) / 128.0) * log(10000.0));
    double ang = (double)t * theta;
    ctab[idx] = (float)cos(ang);
    stab[idx] = (float)sin(ang);
}

// --------------------------- RoPE apply (in place) --------------------------
__global__ void rope_kernel(float* __restrict__ X,
                            const float* __restrict__ ctab,
                            const float* __restrict__ stab,
                            int H) {
    int idx = blockIdx.x * blockDim.x + threadIdx.x;
    int j = idx & 63;
    int r = idx >> 6;
    int h = r % H;
    int r2 = r / H;
    int t = r2 % SEQ_T;
    int b = r2 / SEQ_T;
    float* p = X + ((size_t)(b * SEQ_T + t) * H + h) * HEAD_DIM;
    float c = ctab[t * 64 + j];
    float s = stab[t * 64 + j];
    float x1 = p[j];
    float x2 = p[j + 64];
    p[j]      = x1 * c - x2 * s;
    p[j + 64] = x2 * c + x1 * s;
}

// --------------------------- tf32 GEMM (NT) ---------------------------------
// C[M,N] = A[M,K] @ W[N,K]^T (+bias). 128x128 tile, BK=32, 256 threads.
// smem stride 36 words -> conflict-free (4g+t)%32 fragment loads.
#define GST 36
#define GAB (128 * GST)    // words per buffer

__global__ void gemm_tf32(const float* __restrict__ A, const float* __restrict__ W,
                          const float* __restrict__ bias, float* __restrict__ C,
                          int M, int N, int K) {
    extern __shared__ uint32_t gsm[];
    // [buf] A: gsm + buf*GAB ; W: gsm + 2*GAB + buf*GAB
    int tid = threadIdx.x;
    int wid = tid >> 5, lane = tid & 31;
    int wm = wid & 3, wn = wid >> 2;       // warp tile: rows wm*32, cols wn*64
    int g = lane >> 2, t = lane & 3;

    int bx = blockIdx.x, by = blockIdx.y;
    const float* Ablk = A + (size_t)by * 128 * K;
    const float* Wblk = W + (size_t)bx * 128 * K;

    int lrow = tid >> 3;            // 0..31
    int lc4  = (tid & 7) * 4;       // 0..28

    float acc[2][8][4];
#pragma unroll
    for (int i = 0; i < 2; i++)
#pragma unroll
        for (int j = 0; j < 8; j++)
#pragma unroll
            for (int u = 0; u < 4; u++) acc[i][j][u] = 0.f;

    int ntiles = K / 32;

    // preload tile 0
    {
        uint32_t* As = gsm;
        uint32_t* Ws = gsm + 2 * GAB;
#pragma unroll
        for (int p = 0; p < 4; p++) {
            int r = lrow + 32 * p;
            float4 av = *(const float4*)(Ablk + (size_t)r * K + lc4);
            float4 wv = *(const float4*)(Wblk + (size_t)r * K + lc4);
            uint32_t* ad = As + r * GST + lc4;
            uint32_t* wd = Ws + r * GST + lc4;
            ad[0] = f2tf(av.x); ad[1] = f2tf(av.y); ad[2] = f2tf(av.z); ad[3] = f2tf(av.w);
            wd[0] = f2tf(wv.x); wd[1] = f2tf(wv.y); wd[2] = f2tf(wv.z); wd[3] = f2tf(wv.w);
        }
    }
    __syncthreads();

    for (int tt = 0; tt < ntiles; tt++) {
        float4 pa[4], pw[4];
        bool more = (tt + 1 < ntiles);
        if (more) {
            int kt = (tt + 1) * 32;
#pragma unroll
            for (int p = 0; p < 4; p++) {
                int r = lrow + 32 * p;
                pa[p] = *(const float4*)(Ablk + (size_t)r * K + kt + lc4);
                pw[p] = *(const float4*)(Wblk + (size_t)r * K + kt + lc4);
            }
        }

        const uint32_t* As = gsm + (tt & 1) * GAB;
        const uint32_t* Ws = gsm + 2 * GAB + (tt & 1) * GAB;
#pragma unroll
        for (int ks = 0; ks < 4; ks++) {
            uint32_t a[2][4], b[8][2];
#pragma unroll
            for (int mf = 0; mf < 2; mf++) {
                int rb = wm * 32 + mf * 16;
                a[mf][0] = As[(rb + g) * GST + ks * 8 + t];
                a[mf][1] = As[(rb + g + 8) * GST + ks * 8 + t];
                a[mf][2] = As[(rb + g) * GST + ks * 8 + t + 4];
                a[mf][3] = As[(rb + g + 8) * GST + ks * 8 + t + 4];
            }
#pragma unroll
            for (int nf = 0; nf < 8; nf++) {
                int nb = wn * 64 + nf * 8;
                b[nf][0] = Ws[(nb + g) * GST + ks * 8 + t];
                b[nf][1] = Ws[(nb + g) * GST + ks * 8 + t + 4];
            }
#pragma unroll
            for (int mf = 0; mf < 2; mf++)
#pragma unroll
                for (int nf = 0; nf < 8; nf++)
                    mma_tf32(acc[mf][nf], a[mf], b[nf]);
        }

        if (more) {
            uint32_t* Ad = gsm + ((tt + 1) & 1) * GAB;
            uint32_t* Wd = gsm + 2 * GAB + ((tt + 1) & 1) * GAB;
#pragma unroll
            for (int p = 0; p < 4; p++) {
                int r = lrow + 32 * p;
                uint32_t* ad = Ad + r * GST + lc4;
                uint32_t* wd = Wd + r * GST + lc4;
                ad[0] = f2tf(pa[p].x); ad[1] = f2tf(pa[p].y);
                ad[2] = f2tf(pa[p].z); ad[3] = f2tf(pa[p].w);
                wd[0] = f2tf(pw[p].x); wd[1] = f2tf(pw[p].y);
                wd[2] = f2tf(pw[p].z); wd[3] = f2tf(pw[p].w);
            }
        }
        __syncthreads();
    }

    // epilogue
#pragma unroll
    for (int mf = 0; mf < 2; mf++) {
        int r0 = by * 128 + wm * 32 + mf * 16 + g;
#pragma unroll
        for (int nf = 0; nf < 8; nf++) {
            int col = bx * 128 + wn * 64 + nf * 8 + 2 * t;
            float b0 = bias ? bias[col] : 0.f;
            float b1 = bias ? bias[col + 1] : 0.f;
            float2 v0 = {acc[mf][nf][0] + b0, acc[mf][nf][1] + b1};
            float2 v1 = {acc[mf][nf][2] + b0, acc[mf][nf][3] + b1};
            *(float2*)(C + (size_t)r0 * N + col) = v0;
            *(float2*)(C + (size_t)(r0 + 8) * N + col) = v1;
        }
    }
}

// ----------------------- tf32 flash attention -------------------------------
// BM=BN=64, 128 threads (4 warps x 16 q-rows). Q frags in regs; K/V/P in smem.
#define KST 132   // K smem stride (words): (4g+t) pattern conflict-free
#define VST 136   // V smem stride: (8t+g) pattern conflict-free
#define PST 68    // per-warp P stride

#define SM_K  0
#define SM_V  (64 * KST)
#define SM_P  (SM_V + 64 * VST)
#define SM_WORDS (SM_P + 4 * 16 * PST)

__global__ void __launch_bounds__(128)
flash_tf32(const float* __restrict__ Q, const float* __restrict__ K,
           const float* __restrict__ V, float* __restrict__ O) {
    extern __shared__ uint32_t fsm[];
    uint32_t* Ks = fsm + SM_K;
    uint32_t* Vs = fsm + SM_V;

    int tid = threadIdx.x;
    int wid = tid >> 5, lane = tid & 31;
    int g = lane >> 2, t = lane & 3;
    int qt = gridDim.x - 1 - blockIdx.x;   // heavy blocks first
    int h  = blockIdx.y;
    int b  = blockIdx.z;
    int kvh = h >> 2;
    int q0 = qt * 64;
    const float scale = 0.08838834764831845f;  // 1/sqrt(128)

    uint32_t* Pw = fsm + SM_P + wid * (16 * PST);

    // ---- stage Q tile (scaled, tf32) into Ks, then build register frags ----
#pragma unroll
    for (int p = 0; p < 16; p++) {
        int idx = tid + 128 * p;
        int row = idx >> 5;
        int c4 = (idx & 31) * 4;
        const float* src = Q + ((size_t)(b * SEQ_T + q0 + row) * N_HEAD + h) * HEAD_DIM + c4;
        float4 v = *(const float4*)src;
        uint32_t* d = Ks + row * KST + c4;
        d[0] = f2tf(v.x * scale); d[1] = f2tf(v.y * scale);
        d[2] = f2tf(v.z * scale); d[3] = f2tf(v.w * scale);
    }
    __syncthreads();

    uint32_t qf[16][4];
    {
        int qr = wid * 16;
#pragma unroll
        for (int ks = 0; ks < 16; ks++) {
            qf[ks][0] = Ks[(qr + g) * KST + ks * 8 + t];
            qf[ks][1] = Ks[(qr + g + 8) * KST + ks * 8 + t];
            qf[ks][2] = Ks[(qr + g) * KST + ks * 8 + t + 4];
            qf[ks][3] = Ks[(qr + g + 8) * KST + ks * 8 + t + 4];
        }
    }

    float o[16][4];
#pragma unroll
    for (int nf = 0; nf < 16; nf++)
#pragma unroll
        for (int u = 0; u < 4; u++) o[nf][u] = 0.f;
    float m0 = -INFINITY, m1 = -INFINITY, l0 = 0.f, l1 = 0.f;

    for (int kt = 0; kt <= qt; kt++) {
        int k0 = kt * 64;
        __syncthreads();   // Ks/Vs reuse safe (covers q-frag reads on 1st iter)
        // ---- load K,V tiles (tf32) ----
#pragma unroll
        for (int p = 0; p < 16; p++) {
            int idx = tid + 128 * p;
            int row = idx >> 5;
            int c4 = (idx & 31) * 4;
            size_t base = ((size_t)(b * SEQ_T + k0 + row) * N_KVH + kvh) * HEAD_DIM + c4;
            float4 kv = *(const float4*)(K + base);
            float4 vv = *(const float4*)(V + base);
            uint32_t* kd = Ks + row * KST + c4;
            uint32_t* vd = Vs + row * VST + c4;
            kd[0] = f2tf(kv.x); kd[1] = f2tf(kv.y); kd[2] = f2tf(kv.z); kd[3] = f2tf(kv.w);
            vd[0] = f2tf(vv.x); vd[1] = f2tf(vv.y); vd[2] = f2tf(vv.z); vd[3] = f2tf(vv.w);
        }
        __syncthreads();

        // ---- S = Q @ K^T ----
        float s[8][4];
#pragma unroll
        for (int nf = 0; nf < 8; nf++)
#pragma unroll
            for (int u = 0; u < 4; u++) s[nf][u] = 0.f;

#pragma unroll
        for (int ks = 0; ks < 16; ks++) {
            uint32_t bfr[8][2];
#pragma unroll
            for (int nf = 0; nf < 8; nf++) {
                bfr[nf][0] = Ks[(nf * 8 + g) * KST + ks * 8 + t];
                bfr[nf][1] = Ks[(nf * 8 + g) * KST + ks * 8 + t + 4];
            }
#pragma unroll
            for (int nf = 0; nf < 8; nf++)
                mma_tf32(s[nf], qf[ks], bfr[nf]);
        }

        // ---- causal mask (diagonal tile) ----
        if (kt == qt) {
            int r0 = q0 + wid * 16 + g;
            int r1 = r0 + 8;
#pragma unroll
            for (int nf = 0; nf < 8; nf++) {
                int c0 = k0 + nf * 8 + 2 * t;
                if (c0 > r0)     s[nf][0] = -INFINITY;
                if (c0 + 1 > r0) s[nf][1] = -INFINITY;
                if (c0 > r1)     s[nf][2] = -INFINITY;
                if (c0 + 1 > r1) s[nf][3] = -INFINITY;
            }
        }

        // ---- online softmax ----
        float rm0 = -INFINITY, rm1 = -INFINITY;
#pragma unroll
        for (int nf = 0; nf < 8; nf++) {
            rm0 = fmaxf(rm0, fmaxf(s[nf][0], s[nf][1]));
            rm1 = fmaxf(rm1, fmaxf(s[nf][2], s[nf][3]));
        }
        rm0 = fmaxf(rm0, __shfl_xor_sync(0xffffffffu, rm0, 1));
        rm0 = fmaxf(rm0, __shfl_xor_sync(0xffffffffu, rm0, 2));
        rm1 = fmaxf(rm1, __shfl_xor_sync(0xffffffffu, rm1, 1));
        rm1 = fmaxf(rm1, __shfl_xor_sync(0xffffffffu, rm1, 2));
        float mn0 = fmaxf(m0, rm0), mn1 = fmaxf(m1, rm1);
        float f0 = __expf(m0 - mn0), f1 = __expf(m1 - mn1);
        m0 = mn0; m1 = mn1;

        float rs0 = 0.f, rs1 = 0.f;
        float pr[8][4];
#pragma unroll
        for (int nf = 0; nf < 8; nf++) {
            pr[nf][0] = __expf(s[nf][0] - mn0);
            pr[nf][1] = __expf(s[nf][1] - mn0);
            pr[nf][2] = __expf(s[nf][2] - mn1);
            pr[nf][3] = __expf(s[nf][3] - mn1);
            rs0 += pr[nf][0] + pr[nf][1];
            rs1 += pr[nf][2] + pr[nf][3];
        }
        rs0 += __shfl_xor_sync(0xffffffffu, rs0, 1);
        rs0 += __shfl_xor_sync(0xffffffffu, rs0, 2);
        rs1 += __shfl_xor_sync(0xffffffffu, rs1, 1);
        rs1 += __shfl_xor_sync(0xffffffffu, rs1, 2);
        l0 = l0 * f0 + rs0;
        l1 = l1 * f1 + rs1;
#pragma unroll
        for (int nf = 0; nf < 16; nf++) {
            o[nf][0] *= f0; o[nf][1] *= f0;
            o[nf][2] *= f1; o[nf][3] *= f1;
        }

        // ---- P to per-warp smem (tf32) ----
#pragma unroll
        for (int nf = 0; nf < 8; nf++) {
            Pw[g * PST + nf * 8 + 2 * t]           = f2tf(pr[nf][0]);
            Pw[g * PST + nf * 8 + 2 * t + 1]       = f2tf(pr[nf][1]);
            Pw[(g + 8) * PST + nf * 8 + 2 * t]     = f2tf(pr[nf][2]);
            Pw[(g + 8) * PST + nf * 8 + 2 * t + 1] = f2tf(pr[nf][3]);
        }
        __syncwarp();

        // ---- O += P @ V ----
#pragma unroll
        for (int ks2 = 0; ks2 < 8; ks2++) {
            uint32_t a[4];
            a[0] = Pw[g * PST + ks2 * 8 + t];
            a[1] = Pw[(g + 8) * PST + ks2 * 8 + t];
            a[2] = Pw[g * PST + ks2 * 8 + t + 4];
            a[3] = Pw[(g + 8) * PST + ks2 * 8 + t + 4];
#pragma unroll
            for (int nf = 0; nf < 16; nf++) {
                uint32_t bfr[2];
                bfr[0] = Vs[(ks2 * 8 + t) * VST + nf * 8 + g];
                bfr[1] = Vs[(ks2 * 8 + t + 4) * VST + nf * 8 + g];
                mma_tf32(o[nf], a, bfr);
            }
        }
    }

    // ---- epilogue ----
    float inv0 = 1.f / l0, inv1 = 1.f / l1;
    int r0 = q0 + wid * 16 + g;
#pragma unroll
    for (int nf = 0; nf < 16; nf++) {
        int col = nf * 8 + 2 * t;
        float* d0 = O + ((size_t)(b * SEQ_T + r0) * N_HEAD + h) * HEAD_DIM + col;
        float* d1 = O + ((size_t)(b * SEQ_T + r0 + 8) * N_HEAD + h) * HEAD_DIM + col;
        float2 v0 = {o[nf][0] * inv0, o[nf][1] * inv0};
        float2 v1 = {o[nf][2] * inv1, o[nf][3] * inv1};
        *(float2*)d0 = v0;
        *(float2*)d1 = v1;
    }
}

// ------------------------------- launch ------------------------------------
extern "C" void kernel_launch(void* const* d_in, const int* in_sizes, int n_in,
                              void* d_out, int out_size) {
    const float* x  = (const float*)d_in[0];
    const float* wq = (const float*)d_in[1];
    const float* wk = (const float*)d_in[2];
    const float* bk = (const float*)d_in[3];
    const float* wv = (const float*)d_in[4];
    const float* bv = (const float*)d_in[5];
    const float* wo = (const float*)d_in[6];
    const float* bo = (const float*)d_in[7];
    float* out = (float*)d_out;

    float *qp, *kp, *vp, *ap, *ct, *st;
    cudaGetSymbolAddress((void**)&qp, g_q);
    cudaGetSymbolAddress((void**)&kp, g_k);
    cudaGetSymbolAddress((void**)&vp, g_v);
    cudaGetSymbolAddress((void**)&ap, g_attn);
    cudaGetSymbolAddress((void**)&ct, g_cos);
    cudaGetSymbolAddress((void**)&st, g_sin);

    size_t gsmem = (size_t)4 * GAB * sizeof(uint32_t);           // 73728 B
    size_t fsmem = (size_t)SM_WORDS * sizeof(uint32_t);          // ~86 KB
    cudaFuncSetAttribute(gemm_tf32, cudaFuncAttributeMaxDynamicSharedMemorySize,
                         (int)gsmem);
    cudaFuncSetAttribute(flash_tf32, cudaFuncAttributeMaxDynamicSharedMemorySize,
                         (int)fsmem);

    rope_table_kernel<<<(SEQ_T * 64) / 256, 256>>>(ct, st);

    gemm_tf32<<<dim3(DIM / 128, M_ROWS / 128), 256, gsmem>>>(x, wq, nullptr, qp,
                                                             M_ROWS, DIM, DIM);
    gemm_tf32<<<dim3((N_KVH * HEAD_DIM) / 128, M_ROWS / 128), 256, gsmem>>>(
        x, wk, bk, kp, M_ROWS, N_KVH * HEAD_DIM, DIM);
    gemm_tf32<<<dim3((N_KVH * HEAD_DIM) / 128, M_ROWS / 128), 256, gsmem>>>(
        x, wv, bv, vp, M_ROWS, N_KVH * HEAD_DIM, DIM);

    rope_kernel<<<((size_t)M_ROWS * N_HEAD * 64) / 256, 256>>>(qp, ct, st, N_HEAD);
    rope_kernel<<<((size_t)M_ROWS * N_KVH * 64) / 256, 256>>>(kp, ct, st, N_KVH);

    flash_tf32<<<dim3(SEQ_T / 64, N_HEAD, BATCH), 128, fsmem>>>(qp, kp, vp, ap);

    gemm_tf32<<<dim3(DIM / 128, M_ROWS / 128), 256, gsmem>>>(ap, wo, bo, out,
                                                             M_ROWS, DIM, DIM);
}

// round 5
// speedup vs baseline: 3.3972x; 1.0968x over previous
#include <cuda_runtime.h>
#include <math.h>
#include <stdint.h>

// ---------------------------------------------------------------------------
// GroupedQueryAttention — tf32 tensor-core v3 (2nd resubmit; infra failures)
//  * Q/K/V pre-rounded to tf32 by producers -> flash has zero in-loop cvt
//  * flash: 256 thr, BM=128/BN=64, cp.async double buffer, shfl P-permute
//  * gemm: cp.async double buffer, 2 blocks/SM
// ---------------------------------------------------------------------------

#define DIM      2048
#define HEAD_DIM 128
#define N_HEAD   16
#define N_KVH    4
#define SEQ_T    2048
#define BATCH    2
#define M_ROWS   (BATCH * SEQ_T)          // 4096

__device__ float g_q   [(size_t)M_ROWS * DIM];
__device__ float g_k   [(size_t)M_ROWS * N_KVH * HEAD_DIM];
__device__ float g_v   [(size_t)M_ROWS * N_KVH * HEAD_DIM];
__device__ float g_attn[(size_t)M_ROWS * DIM];
__device__ float g_cos [SEQ_T * 64];
__device__ float g_sin [SEQ_T * 64];

// ------------------------------ helpers ------------------------------------
__device__ __forceinline__ uint32_t f2tf(float f) {
    uint32_t u;
    asm("cvt.rna.tf32.f32 %0, %1;" : "=r"(u) : "f"(f));
    return u;
}
__device__ __forceinline__ float f2tff(float f) {
    return __uint_as_float(f2tf(f));
}
__device__ __forceinline__ void mma_tf32(float c[4], const uint32_t a[4],
                                         const uint32_t b[2]) {
    asm("mma.sync.aligned.m16n8k8.row.col.f32.tf32.tf32.f32 "
        "{%0,%1,%2,%3},{%4,%5,%6,%7},{%8,%9},{%0,%1,%2,%3};"
        : "+f"(c[0]), "+f"(c[1]), "+f"(c[2]), "+f"(c[3])
        : "r"(a[0]), "r"(a[1]), "r"(a[2]), "r"(a[3]), "r"(b[0]), "r"(b[1]));
}
__device__ __forceinline__ uint32_t smem_u32(const void* p) {
    uint32_t a;
    asm("{.reg .u64 t; cvta.to.shared.u64 t, %1; cvt.u32.u64 %0, t;}"
        : "=r"(a) : "l"(p));
    return a;
}
#define CPA16(dst, src) \
    asm volatile("cp.async.cg.shared.global [%0], [%1], 16;" :: "r"(dst), "l"(src))
#define CPCOMMIT() asm volatile("cp.async.commit_group;")
template <int N> __device__ __forceinline__ void cpwait() {
    asm volatile("cp.async.wait_group %0;" :: "n"(N));
}

// ------------------------- RoPE tables (double) ----------------------------
__global__ void rope_table_kernel(float* ctab, float* stab) {
    int idx = blockIdx.x * blockDim.x + threadIdx.x;
    int t = idx >> 6;
    int j = idx & 63;
    double theta = exp(-((double)(2 * j) / 128.0) * log(10000.0));
    double ang = (double)t * theta;
    ctab[idx] = (float)cos(ang);
    stab[idx] = (float)sin(ang);
}

// -------------------- RoPE apply (in place, scale+tf32-round) ---------------
__global__ void rope_kernel(float* __restrict__ X,
                            const float* __restrict__ ctab,
                            const float* __restrict__ stab,
                            int H, float scale) {
    int idx = blockIdx.x * blockDim.x + threadIdx.x;
    int j = idx & 63;
    int r = idx >> 6;
    int h = r % H;
    int r2 = r / H;
    int t = r2 % SEQ_T;
    int b = r2 / SEQ_T;
    float* p = X + ((size_t)(b * SEQ_T + t) * H + h) * HEAD_DIM;
    float c = ctab[t * 64 + j];
    float s = stab[t * 64 + j];
    float x1 = p[j];
    float x2 = p[j + 64];
    p[j]      = f2tff((x1 * c - x2 * s) * scale);
    p[j + 64] = f2tff((x2 * c + x1 * s) * scale);
}

// --------------------------- tf32 GEMM (NT) ---------------------------------
// C[M,N] = A[M,K] @ W[N,K]^T (+bias). 128x128 tile, BK=32, 256 thr,
// cp.async double buffer, cvt at fragment load. rnd!=0 -> round output to tf32.
#define GST 36
#define GAB (128 * GST)    // words per (matrix, buffer)

__global__ void __launch_bounds__(256, 2)
gemm_tf32(const float* __restrict__ A, const float* __restrict__ W,
          const float* __restrict__ bias, float* __restrict__ C,
          int M, int N, int K, int rnd) {
    extern __shared__ float gsm[];
    int tid = threadIdx.x;
    int wid = tid >> 5, lane = tid & 31;
    int wm = wid & 3, wn = wid >> 2;
    int g = lane >> 2, t = lane & 3;
    int bx = blockIdx.x, by = blockIdx.y;

    const float* Ablk = A + (size_t)by * 128 * K;
    const float* Wblk = W + (size_t)bx * 128 * K;
    int lrow = tid >> 3;            // 0..31
    int lc4  = (tid & 7) * 4;       // 0,4,..28
    uint32_t sbase = smem_u32(gsm);

    float acc[2][8][4];
#pragma unroll
    for (int i = 0; i < 2; i++)
#pragma unroll
        for (int j = 0; j < 8; j++)
#pragma unroll
            for (int u = 0; u < 4; u++) acc[i][j][u] = 0.f;

    int ntiles = K / 32;

    // prologue: issue tile 0 into buffer 0
    {
        uint32_t ab = sbase, wb = sbase + 2u * GAB * 4u;
#pragma unroll
        for (int p = 0; p < 4; p++) {
            int r = lrow + 32 * p;
            CPA16(ab + (r * GST + lc4) * 4, Ablk + (size_t)r * K + lc4);
            CPA16(wb + (r * GST + lc4) * 4, Wblk + (size_t)r * K + lc4);
        }
        CPCOMMIT();
    }

    for (int tt = 0; tt < ntiles; tt++) {
        if (tt + 1 < ntiles) {
            int buf = (tt + 1) & 1;
            int kt = (tt + 1) * 32;
            uint32_t ab = sbase + (uint32_t)buf * GAB * 4u;
            uint32_t wb = sbase + (uint32_t)(2 + buf) * GAB * 4u;
#pragma unroll
            for (int p = 0; p < 4; p++) {
                int r = lrow + 32 * p;
                CPA16(ab + (r * GST + lc4) * 4, Ablk + (size_t)r * K + kt + lc4);
                CPA16(wb + (r * GST + lc4) * 4, Wblk + (size_t)r * K + kt + lc4);
            }
            CPCOMMIT();
            cpwait<1>();
        } else {
            cpwait<0>();
        }
        __syncthreads();

        const float* As = gsm + (size_t)(tt & 1) * GAB;
        const float* Ws = gsm + (size_t)(2 + (tt & 1)) * GAB;
#pragma unroll
        for (int ks = 0; ks < 4; ks++) {
            uint32_t a[2][4], b[8][2];
#pragma unroll
            for (int mf = 0; mf < 2; mf++) {
                int rb = wm * 32 + mf * 16;
                a[mf][0] = f2tf(As[(rb + g) * GST + ks * 8 + t]);
                a[mf][1] = f2tf(As[(rb + g + 8) * GST + ks * 8 + t]);
                a[mf][2] = f2tf(As[(rb + g) * GST + ks * 8 + t + 4]);
                a[mf][3] = f2tf(As[(rb + g + 8) * GST + ks * 8 + t + 4]);
            }
#pragma unroll
            for (int nf = 0; nf < 8; nf++) {
                int nb = wn * 64 + nf * 8;
                b[nf][0] = f2tf(Ws[(nb + g) * GST + ks * 8 + t]);
                b[nf][1] = f2tf(Ws[(nb + g) * GST + ks * 8 + t + 4]);
            }
#pragma unroll
            for (int mf = 0; mf < 2; mf++)
#pragma unroll
                for (int nf = 0; nf < 8; nf++)
                    mma_tf32(acc[mf][nf], a[mf], b[nf]);
        }
        __syncthreads();
    }

    // epilogue
#pragma unroll
    for (int mf = 0; mf < 2; mf++) {
        int r0 = by * 128 + wm * 32 + mf * 16 + g;
#pragma unroll
        for (int nf = 0; nf < 8; nf++) {
            int col = bx * 128 + wn * 64 + nf * 8 + 2 * t;
            float b0 = bias ? bias[col] : 0.f;
            float b1 = bias ? bias[col + 1] : 0.f;
            float v00 = acc[mf][nf][0] + b0, v01 = acc[mf][nf][1] + b1;
            float v10 = acc[mf][nf][2] + b0, v11 = acc[mf][nf][3] + b1;
            if (rnd) { v00 = f2tff(v00); v01 = f2tff(v01);
                       v10 = f2tff(v10); v11 = f2tff(v11); }
            float2 w0 = {v00, v01}, w1 = {v10, v11};
            *(float2*)(C + (size_t)r0 * N + col) = w0;
            *(float2*)(C + (size_t)(r0 + 8) * N + col) = w1;
        }
    }
}

// ----------------------- tf32 flash attention v2 ----------------------------
// 256 threads / 8 warps. BM=128 (warp w: rows w*16..+15), BN=64.
// K/V double-buffered via cp.async (data pre-rounded to tf32 by producers).
// Q fragments register-resident. P permuted C-frag -> A-frag via shfl.
#define KST 132
#define VST 136
#define FK0 0
#define FK1 (64 * KST)
#define FV0 (2 * 64 * KST)
#define FV1 (FV0 + 64 * VST)
#define FWORDS (FV1 + 64 * VST)   // 34304 words = 137216 B

__global__ void __launch_bounds__(256, 1)
flash_tf32(const float* __restrict__ Q, const float* __restrict__ K,
           const float* __restrict__ V, float* __restrict__ O) {
    extern __shared__ uint32_t fsm[];
    int tid = threadIdx.x;
    int wid = tid >> 5, lane = tid & 31;
    int g = lane >> 2, t = lane & 3;
    int qt = gridDim.x - 1 - blockIdx.x;   // heavy blocks first
    int h  = blockIdx.y;
    int b  = blockIdx.z;
    int kvh = h >> 2;
    int q0 = qt * 128;
    int ntiles = 2 * qt + 2;

    uint32_t sb = smem_u32(fsm);
    uint32_t kbB[2] = {sb + FK0 * 4u, sb + FK1 * 4u};
    uint32_t vbB[2] = {sb + FV0 * 4u, sb + FV1 * 4u};

    // ---- prologue: issue K/V tile 0 into buffer 0 ----
    {
        int k0 = 0;
#pragma unroll
        for (int p = 0; p < 8; p++) {
            int idx = tid + 256 * p;
            int row = idx >> 5;
            int c4 = (idx & 31) * 4;
            size_t gb = ((size_t)(b * SEQ_T + k0 + row) * N_KVH + kvh) * HEAD_DIM + c4;
            CPA16(kbB[0] + (row * KST + c4) * 4, K + gb);
            CPA16(vbB[0] + (row * VST + c4) * 4, V + gb);
        }
        CPCOMMIT();
    }

    // ---- stage Q tile (already tf32+scaled) into buffer 1 ----
#pragma unroll
    for (int p = 0; p < 16; p++) {
        int idx = tid + 256 * p;
        int row = idx >> 5;
        int c4 = (idx & 31) * 4;
        const uint4 v = *(const uint4*)(Q +
            ((size_t)(b * SEQ_T + q0 + row) * N_HEAD + h) * HEAD_DIM + c4);
        uint32_t* dst = (row < 64)
            ? (fsm + FK1 + row * KST + c4)
            : (fsm + FV1 + (row - 64) * VST + c4);
        *(uint4*)dst = v;
    }
    __syncthreads();

    // ---- Q fragments to registers ----
    uint32_t qf[16][4];
    {
        const uint32_t* qs;
        int str, r0;
        if (wid < 4) { qs = fsm + FK1; str = KST; r0 = wid * 16; }
        else         { qs = fsm + FV1; str = VST; r0 = (wid - 4) * 16; }
#pragma unroll
        for (int ks = 0; ks < 16; ks++) {
            qf[ks][0] = qs[(r0 + g) * str + ks * 8 + t];
            qf[ks][1] = qs[(r0 + g + 8) * str + ks * 8 + t];
            qf[ks][2] = qs[(r0 + g) * str + ks * 8 + t + 4];
            qf[ks][3] = qs[(r0 + g + 8) * str + ks * 8 + t + 4];
        }
    }
    __syncthreads();   // qf reads done before loop overwrites buffer 1

    float o[16][4];
#pragma unroll
    for (int nf = 0; nf < 16; nf++)
#pragma unroll
        for (int u = 0; u < 4; u++) o[nf][u] = 0.f;
    float m0 = -INFINITY, m1 = -INFINITY, l0 = 0.f, l1 = 0.f;

    int qrow0 = q0 + wid * 16 + g;       // this thread's first q row
    int srcA = (lane & 28) | (t >> 1);   // shfl src for P cols t
    int srcB = srcA + 2;                 // shfl src for P cols t+4

    for (int kt = 0; kt < ntiles; kt++) {
        // prefetch next tile
        if (kt + 1 < ntiles) {
            int buf = (kt + 1) & 1;
            int k0n = (kt + 1) * 64;
#pragma unroll
            for (int p = 0; p < 8; p++) {
                int idx = tid + 256 * p;
                int row = idx >> 5;
                int c4 = (idx & 31) * 4;
                size_t gb = ((size_t)(b * SEQ_T + k0n + row) * N_KVH + kvh) * HEAD_DIM + c4;
                CPA16(kbB[buf] + (row * KST + c4) * 4, K + gb);
                CPA16(vbB[buf] + (row * VST + c4) * 4, V + gb);
            }
            CPCOMMIT();
            cpwait<1>();
        } else {
            cpwait<0>();
        }
        __syncthreads();

        const uint32_t* Ks = fsm + ((kt & 1) ? FK1 : FK0);
        const uint32_t* Vs = fsm + ((kt & 1) ? FV1 : FV0);
        int k0 = kt * 64;

        // ---- S = Q @ K^T ----
        float s[8][4];
#pragma unroll
        for (int nf = 0; nf < 8; nf++)
#pragma unroll
            for (int u = 0; u < 4; u++) s[nf][u] = 0.f;

#pragma unroll
        for (int ks = 0; ks < 16; ks++) {
            uint32_t bfr[8][2];
#pragma unroll
            for (int nf = 0; nf < 8; nf++) {
                bfr[nf][0] = Ks[(nf * 8 + g) * KST + ks * 8 + t];
                bfr[nf][1] = Ks[(nf * 8 + g) * KST + ks * 8 + t + 4];
            }
#pragma unroll
            for (int nf = 0; nf < 8; nf++)
                mma_tf32(s[nf], qf[ks], bfr[nf]);
        }

        // ---- causal mask (only tiles straddling the diagonal) ----
        if (k0 + 63 > qrow0) {
            int r0 = qrow0, r1 = qrow0 + 8;
#pragma unroll
            for (int nf = 0; nf < 8; nf++) {
                int c0 = k0 + nf * 8 + 2 * t;
                if (c0 > r0)     s[nf][0] = -INFINITY;
                if (c0 + 1 > r0) s[nf][1] = -INFINITY;
                if (c0 > r1)     s[nf][2] = -INFINITY;
                if (c0 + 1 > r1) s[nf][3] = -INFINITY;
            }
        }

        // ---- online softmax ----
        float rm0 = -INFINITY, rm1 = -INFINITY;
#pragma unroll
        for (int nf = 0; nf < 8; nf++) {
            rm0 = fmaxf(rm0, fmaxf(s[nf][0], s[nf][1]));
            rm1 = fmaxf(rm1, fmaxf(s[nf][2], s[nf][3]));
        }
        rm0 = fmaxf(rm0, __shfl_xor_sync(0xffffffffu, rm0, 1));
        rm0 = fmaxf(rm0, __shfl_xor_sync(0xffffffffu, rm0, 2));
        rm1 = fmaxf(rm1, __shfl_xor_sync(0xffffffffu, rm1, 1));
        rm1 = fmaxf(rm1, __shfl_xor_sync(0xffffffffu, rm1, 2));
        float mn0 = fmaxf(m0, rm0), mn1 = fmaxf(m1, rm1);
        float f0 = __expf(m0 - mn0), f1 = __expf(m1 - mn1);
        m0 = mn0; m1 = mn1;

        float rs0 = 0.f, rs1 = 0.f;
#pragma unroll
        for (int nf = 0; nf < 8; nf++) {
            s[nf][0] = __expf(s[nf][0] - mn0);
            s[nf][1] = __expf(s[nf][1] - mn0);
            s[nf][2] = __expf(s[nf][2] - mn1);
            s[nf][3] = __expf(s[nf][3] - mn1);
            rs0 += s[nf][0] + s[nf][1];
            rs1 += s[nf][2] + s[nf][3];
        }
        rs0 += __shfl_xor_sync(0xffffffffu, rs0, 1);
        rs0 += __shfl_xor_sync(0xffffffffu, rs0, 2);
        rs1 += __shfl_xor_sync(0xffffffffu, rs1, 1);
        rs1 += __shfl_xor_sync(0xffffffffu, rs1, 2);
        l0 = l0 * f0 + rs0;
        l1 = l1 * f1 + rs1;
#pragma unroll
        for (int nf = 0; nf < 16; nf++) {
            o[nf][0] *= f0; o[nf][1] *= f0;
            o[nf][2] *= f1; o[nf][3] *= f1;
        }

        // ---- O += P @ V (A-frags via intra-quad shfl permutation) ----
#pragma unroll
        for (int ks2 = 0; ks2 < 8; ks2++) {
            uint32_t p0 = f2tf(s[ks2][0]), p1 = f2tf(s[ks2][1]);
            uint32_t p2 = f2tf(s[ks2][2]), p3 = f2tf(s[ks2][3]);
            uint32_t x0 = __shfl_sync(0xffffffffu, p0, srcA);
            uint32_t y0 = __shfl_sync(0xffffffffu, p1, srcA);
            uint32_t x1 = __shfl_sync(0xffffffffu, p2, srcA);
            uint32_t y1 = __shfl_sync(0xffffffffu, p3, srcA);
            uint32_t x2 = __shfl_sync(0xffffffffu, p0, srcB);
            uint32_t y2 = __shfl_sync(0xffffffffu, p1, srcB);
            uint32_t x3 = __shfl_sync(0xffffffffu, p2, srcB);
            uint32_t y3 = __shfl_sync(0xffffffffu, p3, srcB);
            uint32_t a[4];
            a[0] = (t & 1) ? y0 : x0;
            a[1] = (t & 1) ? y1 : x1;
            a[2] = (t & 1) ? y2 : x2;
            a[3] = (t & 1) ? y3 : x3;
#pragma unroll
            for (int nf = 0; nf < 16; nf++) {
                uint32_t bfr[2];
                bfr[0] = Vs[(ks2 * 8 + t) * VST + nf * 8 + g];
                bfr[1] = Vs[(ks2 * 8 + t + 4) * VST + nf * 8 + g];
                mma_tf32(o[nf], a, bfr);
            }
        }
        __syncthreads();   // all buffer reads done before next prefetch overwrites
    }

    // ---- epilogue ----
    float inv0 = 1.f / l0, inv1 = 1.f / l1;
#pragma unroll
    for (int nf = 0; nf < 16; nf++) {
        int col = nf * 8 + 2 * t;
        float* d0 = O + ((size_t)(b * SEQ_T + qrow0) * N_HEAD + h) * HEAD_DIM + col;
        float* d1 = O + ((size_t)(b * SEQ_T + qrow0 + 8) * N_HEAD + h) * HEAD_DIM + col;
        float2 v0 = {o[nf][0] * inv0, o[nf][1] * inv0};
        float2 v1 = {o[nf][2] * inv1, o[nf][3] * inv1};
        *(float2*)d0 = v0;
        *(float2*)d1 = v1;
    }
}

// ------------------------------- launch ------------------------------------
extern "C" void kernel_launch(void* const* d_in, const int* in_sizes, int n_in,
                              void* d_out, int out_size) {
    const float* x  = (const float*)d_in[0];
    const float* wq = (const float*)d_in[1];
    const float* wk = (const float*)d_in[2];
    const float* bk = (const float*)d_in[3];
    const float* wv = (const float*)d_in[4];
    const float* bv = (const float*)d_in[5];
    const float* wo = (const float*)d_in[6];
    const float* bo = (const float*)d_in[7];
    float* out = (float*)d_out;

    float *qp, *kp, *vp, *ap, *ct, *st;
    cudaGetSymbolAddress((void**)&qp, g_q);
    cudaGetSymbolAddress((void**)&kp, g_k);
    cudaGetSymbolAddress((void**)&vp, g_v);
    cudaGetSymbolAddress((void**)&ap, g_attn);
    cudaGetSymbolAddress((void**)&ct, g_cos);
    cudaGetSymbolAddress((void**)&st, g_sin);

    size_t gsmem = (size_t)4 * GAB * sizeof(float);       // 73728 B
    size_t fsmem = (size_t)FWORDS * sizeof(uint32_t);     // 137216 B
    cudaFuncSetAttribute(gemm_tf32, cudaFuncAttributeMaxDynamicSharedMemorySize,
                         (int)gsmem);
    cudaFuncSetAttribute(flash_tf32, cudaFuncAttributeMaxDynamicSharedMemorySize,
                         (int)fsmem);

    rope_table_kernel<<<(SEQ_T * 64) / 256, 256>>>(ct, st);

    gemm_tf32<<<dim3(DIM / 128, M_ROWS / 128), 256, gsmem>>>(
        x, wq, nullptr, qp, M_ROWS, DIM, DIM, 0);
    gemm_tf32<<<dim3((N_KVH * HEAD_DIM) / 128, M_ROWS / 128), 256, gsmem>>>(
        x, wk, bk, kp, M_ROWS, N_KVH * HEAD_DIM, DIM, 0);
    gemm_tf32<<<dim3((N_KVH * HEAD_DIM) / 128, M_ROWS / 128), 256, gsmem>>>(
        x, wv, bv, vp, M_ROWS, N_KVH * HEAD_DIM, DIM, 1);   // V -> tf32

    const float qscale = 0.08838834764831845f;   // 1/sqrt(128)
    rope_kernel<<<((size_t)M_ROWS * N_HEAD * 64) / 256, 256>>>(qp, ct, st,
                                                               N_HEAD, qscale);
    rope_kernel<<<((size_t)M_ROWS * N_KVH * 64) / 256, 256>>>(kp, ct, st,
                                                              N_KVH, 1.0f);

    flash_tf32<<<dim3(SEQ_T / 128, N_HEAD, BATCH), 256, fsmem>>>(qp, kp, vp, ap);

    gemm_tf32<<<dim3(DIM / 128, M_ROWS / 128), 256, gsmem>>>(
        ap, wo, bo, out, M_ROWS, DIM, DIM, 0);
}

// round 6
// speedup vs baseline: 3.5773x; 1.0530x over previous
#include <cuda_runtime.h>
#include <math.h>
#include <stdint.h>

// ---------------------------------------------------------------------------
// GroupedQueryAttention — tf32 v4
//  * inputs pre-rounded to tf32 once -> zero cvt in all GEMM/flash hot loops
//  * fused QKV projection (768 blocks; fixes K/V under-fill)
//  * flash epilogue emits tf32 -> out-proj also cvt-free
// ---------------------------------------------------------------------------

#define DIM      2048
#define HEAD_DIM 128
#define N_HEAD   16
#define N_KVH    4
#define SEQ_T    2048
#define BATCH    2
#define M_ROWS   (BATCH * SEQ_T)          // 4096
#define NQKV     (DIM + 2 * N_KVH * HEAD_DIM)   // 3072

__device__ float g_q   [(size_t)M_ROWS * DIM];
__device__ float g_k   [(size_t)M_ROWS * N_KVH * HEAD_DIM];
__device__ float g_v   [(size_t)M_ROWS * N_KVH * HEAD_DIM];
__device__ float g_attn[(size_t)M_ROWS * DIM];
__device__ float g_x   [(size_t)M_ROWS * DIM];            // rounded x
__device__ float g_wqkv[(size_t)NQKV * DIM];              // rounded wq|wk|wv
__device__ float g_wo  [(size_t)DIM * DIM];               // rounded wo
__device__ float g_cos [SEQ_T * 64];
__device__ float g_sin [SEQ_T * 64];

// ------------------------------ helpers ------------------------------------
__device__ __forceinline__ uint32_t f2tf(float f) {
    uint32_t u;
    asm("cvt.rna.tf32.f32 %0, %1;" : "=r"(u) : "f"(f));
    return u;
}
__device__ __forceinline__ float f2tff(float f) {
    return __uint_as_float(f2tf(f));
}
__device__ __forceinline__ void mma_tf32(float c[4], const uint32_t a[4],
                                         const uint32_t b[2]) {
    asm("mma.sync.aligned.m16n8k8.row.col.f32.tf32.tf32.f32 "
        "{%0,%1,%2,%3},{%4,%5,%6,%7},{%8,%9},{%0,%1,%2,%3};"
        : "+f"(c[0]), "+f"(c[1]), "+f"(c[2]), "+f"(c[3])
        : "r"(a[0]), "r"(a[1]), "r"(a[2]), "r"(a[3]), "r"(b[0]), "r"(b[1]));
}
__device__ __forceinline__ uint32_t smem_u32(const void* p) {
    uint32_t a;
    asm("{.reg .u64 t; cvta.to.shared.u64 t, %1; cvt.u32.u64 %0, t;}"
        : "=r"(a) : "l"(p));
    return a;
}
#define CPA16(dst, src) \
    asm volatile("cp.async.cg.shared.global [%0], [%1], 16;" :: "r"(dst), "l"(src))
#define CPCOMMIT() asm volatile("cp.async.commit_group;")
template <int N> __device__ __forceinline__ void cpwait() {
    asm volatile("cp.async.wait_group %0;" :: "n"(N));
}

// ------------------------- pre-round to tf32 --------------------------------
__global__ void rnd_kernel(const float4* __restrict__ src,
                           float4* __restrict__ dst, int n4) {
    int i = blockIdx.x * blockDim.x + threadIdx.x;
    if (i < n4) {
        float4 v = src[i];
        v.x = f2tff(v.x); v.y = f2tff(v.y);
        v.z = f2tff(v.z); v.w = f2tff(v.w);
        dst[i] = v;
    }
}

// ------------------------- RoPE tables (double) ----------------------------
__global__ void rope_table_kernel(float* ctab, float* stab) {
    int idx = blockIdx.x * blockDim.x + threadIdx.x;
    int t = idx >> 6;
    int j = idx & 63;
    double theta = exp(-((double)(2 * j) / 128.0) * log(10000.0));
    double ang = (double)t * theta;
    ctab[idx] = (float)cos(ang);
    stab[idx] = (float)sin(ang);
}

// -------------------- RoPE apply (in place, scale+tf32-round) ---------------
__global__ void rope_kernel(float* __restrict__ X,
                            const float* __restrict__ ctab,
                            const float* __restrict__ stab,
                            int H, float scale) {
    int idx = blockIdx.x * blockDim.x + threadIdx.x;
    int j = idx & 63;
    int r = idx >> 6;
    int h = r % H;
    int r2 = r / H;
    int t = r2 % SEQ_T;
    int b = r2 / SEQ_T;
    float* p = X + ((size_t)(b * SEQ_T + t) * H + h) * HEAD_DIM;
    float c = ctab[t * 64 + j];
    float s = stab[t * 64 + j];
    float x1 = p[j];
    float x2 = p[j + 64];
    p[j]      = f2tff((x1 * c - x2 * s) * scale);
    p[j + 64] = f2tff((x2 * c + x1 * s) * scale);
}

// --------------------------- tf32 GEMM core ---------------------------------
// inputs pre-rounded: zero cvt in hot loop. 128x128 tile, BK=32, 256 thr.
#define GST 36
#define GAB (128 * GST)

struct GemmOut {
    float* C; const float* bias; int ldn; int col0; int rnd;
};

__device__ __forceinline__ void gemm_body(
    const float* __restrict__ Ablk, const float* __restrict__ Wblk,
    int K, int by, const GemmOut& out, float* gsm) {
    int tid = threadIdx.x;
    int wid = tid >> 5, lane = tid & 31;
    int wm = wid & 3, wn = wid >> 2;
    int g = lane >> 2, t = lane & 3;
    int lrow = tid >> 3;
    int lc4  = (tid & 7) * 4;
    uint32_t sbase = smem_u32(gsm);

    float acc[2][8][4];
#pragma unroll
    for (int i = 0; i < 2; i++)
#pragma unroll
        for (int j = 0; j < 8; j++)
#pragma unroll
            for (int u = 0; u < 4; u++) acc[i][j][u] = 0.f;

    int ntiles = K / 32;

    {
        uint32_t ab = sbase, wb = sbase + 2u * GAB * 4u;
#pragma unroll
        for (int p = 0; p < 4; p++) {
            int r = lrow + 32 * p;
            CPA16(ab + (r * GST + lc4) * 4, Ablk + (size_t)r * K + lc4);
            CPA16(wb + (r * GST + lc4) * 4, Wblk + (size_t)r * K + lc4);
        }
        CPCOMMIT();
    }

    for (int tt = 0; tt < ntiles; tt++) {
        if (tt + 1 < ntiles) {
            int buf = (tt + 1) & 1;
            int kt = (tt + 1) * 32;
            uint32_t ab = sbase + (uint32_t)buf * GAB * 4u;
            uint32_t wb = sbase + (uint32_t)(2 + buf) * GAB * 4u;
#pragma unroll
            for (int p = 0; p < 4; p++) {
                int r = lrow + 32 * p;
                CPA16(ab + (r * GST + lc4) * 4, Ablk + (size_t)r * K + kt + lc4);
                CPA16(wb + (r * GST + lc4) * 4, Wblk + (size_t)r * K + kt + lc4);
            }
            CPCOMMIT();
            cpwait<1>();
        } else {
            cpwait<0>();
        }
        __syncthreads();

        const uint32_t* As = (const uint32_t*)gsm + (size_t)(tt & 1) * GAB;
        const uint32_t* Ws = (const uint32_t*)gsm + (size_t)(2 + (tt & 1)) * GAB;
#pragma unroll
        for (int ks = 0; ks < 4; ks++) {
            uint32_t a[2][4], b[8][2];
#pragma unroll
            for (int mf = 0; mf < 2; mf++) {
                int rb = wm * 32 + mf * 16;
                a[mf][0] = As[(rb + g) * GST + ks * 8 + t];
                a[mf][1] = As[(rb + g + 8) * GST + ks * 8 + t];
                a[mf][2] = As[(rb + g) * GST + ks * 8 + t + 4];
                a[mf][3] = As[(rb + g + 8) * GST + ks * 8 + t + 4];
            }
#pragma unroll
            for (int nf = 0; nf < 8; nf++) {
                int nb = wn * 64 + nf * 8;
                b[nf][0] = Ws[(nb + g) * GST + ks * 8 + t];
                b[nf][1] = Ws[(nb + g) * GST + ks * 8 + t + 4];
            }
#pragma unroll
            for (int mf = 0; mf < 2; mf++)
#pragma unroll
                for (int nf = 0; nf < 8; nf++)
                    mma_tf32(acc[mf][nf], a[mf], b[nf]);
        }
        __syncthreads();
    }

    // epilogue
#pragma unroll
    for (int mf = 0; mf < 2; mf++) {
        int r0 = by * 128 + wm * 32 + mf * 16 + g;
#pragma unroll
        for (int nf = 0; nf < 8; nf++) {
            int col = out.col0 + wn * 64 + nf * 8 + 2 * t;
            float b0 = out.bias ? out.bias[col] : 0.f;
            float b1 = out.bias ? out.bias[col + 1] : 0.f;
            float v00 = acc[mf][nf][0] + b0, v01 = acc[mf][nf][1] + b1;
            float v10 = acc[mf][nf][2] + b0, v11 = acc[mf][nf][3] + b1;
            if (out.rnd) { v00 = f2tff(v00); v01 = f2tff(v01);
                           v10 = f2tff(v10); v11 = f2tff(v11); }
            float2 w0 = {v00, v01}, w1 = {v10, v11};
            *(float2*)(out.C + (size_t)r0 * out.ldn + col) = w0;
            *(float2*)(out.C + (size_t)(r0 + 8) * out.ldn + col) = w1;
        }
    }
}

// plain GEMM (out-projection)
__global__ void __launch_bounds__(256, 2)
gemm_tf32(const float* __restrict__ A, const float* __restrict__ W,
          const float* __restrict__ bias, float* __restrict__ C,
          int N, int K) {
    extern __shared__ float gsm[];
    GemmOut out = {C, bias, N, (int)blockIdx.x * 128, 0};
    gemm_body(A + (size_t)blockIdx.y * 128 * K,
              W + (size_t)blockIdx.x * 128 * K, K, blockIdx.y, out, gsm);
}

// fused QKV GEMM: bx 0..15 -> q, 16..19 -> k(+bk), 20..23 -> v(+bv, tf32)
__global__ void __launch_bounds__(256, 2)
gemm_qkv(const float* __restrict__ A, const float* __restrict__ Wqkv,
         const float* __restrict__ bk, const float* __restrict__ bv,
         float* __restrict__ Q, float* __restrict__ Kt, float* __restrict__ Vt,
         int K) {
    extern __shared__ float gsm[];
    int bx = blockIdx.x;
    GemmOut out;
    if (bx < 16)      out = {Q,  nullptr, DIM, bx * 128, 0};
    else if (bx < 20) out = {Kt, bk, N_KVH * HEAD_DIM, (bx - 16) * 128, 0};
    else              out = {Vt, bv, N_KVH * HEAD_DIM, (bx - 20) * 128, 1};
    gemm_body(A + (size_t)blockIdx.y * 128 * K,
              Wqkv + (size_t)bx * 128 * K, K, blockIdx.y, out, gsm);
}

// ----------------------- tf32 flash attention -------------------------------
// 256 threads / 8 warps. BM=128, BN=64, cp.async double buffer,
// Q frags in regs, P C-frag -> A-frag via intra-quad shfl.
#define KST 132
#define VST 136
#define FK0 0
#define FK1 (64 * KST)
#define FV0 (2 * 64 * KST)
#define FV1 (FV0 + 64 * VST)
#define FWORDS (FV1 + 64 * VST)   // 137216 B

__global__ void __launch_bounds__(256, 1)
flash_tf32(const float* __restrict__ Q, const float* __restrict__ K,
           const float* __restrict__ V, float* __restrict__ O) {
    extern __shared__ uint32_t fsm[];
    int tid = threadIdx.x;
    int wid = tid >> 5, lane = tid & 31;
    int g = lane >> 2, t = lane & 3;
    int qt = gridDim.x - 1 - blockIdx.x;
    int h  = blockIdx.y;
    int b  = blockIdx.z;
    int kvh = h >> 2;
    int q0 = qt * 128;
    int ntiles = 2 * qt + 2;

    uint32_t sb = smem_u32(fsm);
    uint32_t kbB[2] = {sb + FK0 * 4u, sb + FK1 * 4u};
    uint32_t vbB[2] = {sb + FV0 * 4u, sb + FV1 * 4u};

    {
#pragma unroll
        for (int p = 0; p < 8; p++) {
            int idx = tid + 256 * p;
            int row = idx >> 5;
            int c4 = (idx & 31) * 4;
            size_t gb = ((size_t)(b * SEQ_T + row) * N_KVH + kvh) * HEAD_DIM + c4;
            CPA16(kbB[0] + (row * KST + c4) * 4, K + gb);
            CPA16(vbB[0] + (row * VST + c4) * 4, V + gb);
        }
        CPCOMMIT();
    }

#pragma unroll
    for (int p = 0; p < 16; p++) {
        int idx = tid + 256 * p;
        int row = idx >> 5;
        int c4 = (idx & 31) * 4;
        const uint4 v = *(const uint4*)(Q +
            ((size_t)(b * SEQ_T + q0 + row) * N_HEAD + h) * HEAD_DIM + c4);
        uint32_t* dst = (row < 64)
            ? (fsm + FK1 + row * KST + c4)
            : (fsm + FV1 + (row - 64) * VST + c4);
        *(uint4*)dst = v;
    }
    __syncthreads();

    uint32_t qf[16][4];
    {
        const uint32_t* qs;
        int str, r0;
        if (wid < 4) { qs = fsm + FK1; str = KST; r0 = wid * 16; }
        else         { qs = fsm + FV1; str = VST; r0 = (wid - 4) * 16; }
#pragma unroll
        for (int ks = 0; ks < 16; ks++) {
            qf[ks][0] = qs[(r0 + g) * str + ks * 8 + t];
            qf[ks][1] = qs[(r0 + g + 8) * str + ks * 8 + t];
            qf[ks][2] = qs[(r0 + g) * str + ks * 8 + t + 4];
            qf[ks][3] = qs[(r0 + g + 8) * str + ks * 8 + t + 4];
        }
    }
    __syncthreads();

    float o[16][4];
#pragma unroll
    for (int nf = 0; nf < 16; nf++)
#pragma unroll
        for (int u = 0; u < 4; u++) o[nf][u] = 0.f;
    float m0 = -INFINITY, m1 = -INFINITY, l0 = 0.f, l1 = 0.f;

    int qrow0 = q0 + wid * 16 + g;
    int srcA = (lane & 28) | (t >> 1);
    int srcB = srcA + 2;

    for (int kt = 0; kt < ntiles; kt++) {
        if (kt + 1 < ntiles) {
            int buf = (kt + 1) & 1;
            int k0n = (kt + 1) * 64;
#pragma unroll
            for (int p = 0; p < 8; p++) {
                int idx = tid + 256 * p;
                int row = idx >> 5;
                int c4 = (idx & 31) * 4;
                size_t gb = ((size_t)(b * SEQ_T + k0n + row) * N_KVH + kvh) * HEAD_DIM + c4;
                CPA16(kbB[buf] + (row * KST + c4) * 4, K + gb);
                CPA16(vbB[buf] + (row * VST + c4) * 4, V + gb);
            }
            CPCOMMIT();
            cpwait<1>();
        } else {
            cpwait<0>();
        }
        __syncthreads();

        const uint32_t* Ks = fsm + ((kt & 1) ? FK1 : FK0);
        const uint32_t* Vs = fsm + ((kt & 1) ? FV1 : FV0);
        int k0 = kt * 64;

        float s[8][4];
#pragma unroll
        for (int nf = 0; nf < 8; nf++)
#pragma unroll
            for (int u = 0; u < 4; u++) s[nf][u] = 0.f;

#pragma unroll
        for (int ks = 0; ks < 16; ks++) {
            uint32_t bfr[8][2];
#pragma unroll
            for (int nf = 0; nf < 8; nf++) {
                bfr[nf][0] = Ks[(nf * 8 + g) * KST + ks * 8 + t];
                bfr[nf][1] = Ks[(nf * 8 + g) * KST + ks * 8 + t + 4];
            }
#pragma unroll
            for (int nf = 0; nf < 8; nf++)
                mma_tf32(s[nf], qf[ks], bfr[nf]);
        }

        if (k0 + 63 > qrow0) {
            int r0 = qrow0, r1 = qrow0 + 8;
#pragma unroll
            for (int nf = 0; nf < 8; nf++) {
                int c0 = k0 + nf * 8 + 2 * t;
                if (c0 > r0)     s[nf][0] = -INFINITY;
                if (c0 + 1 > r0) s[nf][1] = -INFINITY;
                if (c0 > r1)     s[nf][2] = -INFINITY;
                if (c0 + 1 > r1) s[nf][3] = -INFINITY;
            }
        }

        float rm0 = -INFINITY, rm1 = -INFINITY;
#pragma unroll
        for (int nf = 0; nf < 8; nf++) {
            rm0 = fmaxf(rm0, fmaxf(s[nf][0], s[nf][1]));
            rm1 = fmaxf(rm1, fmaxf(s[nf][2], s[nf][3]));
        }
        rm0 = fmaxf(rm0, __shfl_xor_sync(0xffffffffu, rm0, 1));
        rm0 = fmaxf(rm0, __shfl_xor_sync(0xffffffffu, rm0, 2));
        rm1 = fmaxf(rm1, __shfl_xor_sync(0xffffffffu, rm1, 1));
        rm1 = fmaxf(rm1, __shfl_xor_sync(0xffffffffu, rm1, 2));
        float mn0 = fmaxf(m0, rm0), mn1 = fmaxf(m1, rm1);
        float f0 = __expf(m0 - mn0), f1 = __expf(m1 - mn1);
        m0 = mn0; m1 = mn1;

        float rs0 = 0.f, rs1 = 0.f;
#pragma unroll
        for (int nf = 0; nf < 8; nf++) {
            s[nf][0] = __expf(s[nf][0] - mn0);
            s[nf][1] = __expf(s[nf][1] - mn0);
            s[nf][2] = __expf(s[nf][2] - mn1);
            s[nf][3] = __expf(s[nf][3] - mn1);
            rs0 += s[nf][0] + s[nf][1];
            rs1 += s[nf][2] + s[nf][3];
        }
        rs0 += __shfl_xor_sync(0xffffffffu, rs0, 1);
        rs0 += __shfl_xor_sync(0xffffffffu, rs0, 2);
        rs1 += __shfl_xor_sync(0xffffffffu, rs1, 1);
        rs1 += __shfl_xor_sync(0xffffffffu, rs1, 2);
        l0 = l0 * f0 + rs0;
        l1 = l1 * f1 + rs1;
#pragma unroll
        for (int nf = 0; nf < 16; nf++) {
            o[nf][0] *= f0; o[nf][1] *= f0;
            o[nf][2] *= f1; o[nf][3] *= f1;
        }

#pragma unroll
        for (int ks2 = 0; ks2 < 8; ks2++) {
            uint32_t p0 = f2tf(s[ks2][0]), p1 = f2tf(s[ks2][1]);
            uint32_t p2 = f2tf(s[ks2][2]), p3 = f2tf(s[ks2][3]);
            uint32_t x0 = __shfl_sync(0xffffffffu, p0, srcA);
            uint32_t y0 = __shfl_sync(0xffffffffu, p1, srcA);
            uint32_t x1 = __shfl_sync(0xffffffffu, p2, srcA);
            uint32_t y1 = __shfl_sync(0xffffffffu, p3, srcA);
            uint32_t x2 = __shfl_sync(0xffffffffu, p0, srcB);
            uint32_t y2 = __shfl_sync(0xffffffffu, p1, srcB);
            uint32_t x3 = __shfl_sync(0xffffffffu, p2, srcB);
            uint32_t y3 = __shfl_sync(0xffffffffu, p3, srcB);
            uint32_t a[4];
            a[0] = (t & 1) ? y0 : x0;
            a[1] = (t & 1) ? y1 : x1;
            a[2] = (t & 1) ? y2 : x2;
            a[3] = (t & 1) ? y3 : x3;
#pragma unroll
            for (int nf = 0; nf < 16; nf++) {
                uint32_t bfr[2];
                bfr[0] = Vs[(ks2 * 8 + t) * VST + nf * 8 + g];
                bfr[1] = Vs[(ks2 * 8 + t + 4) * VST + nf * 8 + g];
                mma_tf32(o[nf], a, bfr);
            }
        }
        __syncthreads();
    }

    // epilogue: normalize, round to tf32 (feeds cvt-free out-projection)
    float inv0 = 1.f / l0, inv1 = 1.f / l1;
#pragma unroll
    for (int nf = 0; nf < 16; nf++) {
        int col = nf * 8 + 2 * t;
        float* d0 = O + ((size_t)(b * SEQ_T + qrow0) * N_HEAD + h) * HEAD_DIM + col;
        float* d1 = O + ((size_t)(b * SEQ_T + qrow0 + 8) * N_HEAD + h) * HEAD_DIM + col;
        float2 v0 = {f2tff(o[nf][0] * inv0), f2tff(o[nf][1] * inv0)};
        float2 v1 = {f2tff(o[nf][2] * inv1), f2tff(o[nf][3] * inv1)};
        *(float2*)d0 = v0;
        *(float2*)d1 = v1;
    }
}

// ------------------------------- launch ------------------------------------
extern "C" void kernel_launch(void* const* d_in, const int* in_sizes, int n_in,
                              void* d_out, int out_size) {
    const float* x  = (const float*)d_in[0];
    const float* wq = (const float*)d_in[1];
    const float* wk = (const float*)d_in[2];
    const float* bk = (const float*)d_in[3];
    const float* wv = (const float*)d_in[4];
    const float* bv = (const float*)d_in[5];
    const float* wo = (const float*)d_in[6];
    const float* bo = (const float*)d_in[7];
    float* out = (float*)d_out;

    float *qp, *kp, *vp, *ap, *xp, *wqkv, *wop, *ct, *st;
    cudaGetSymbolAddress((void**)&qp, g_q);
    cudaGetSymbolAddress((void**)&kp, g_k);
    cudaGetSymbolAddress((void**)&vp, g_v);
    cudaGetSymbolAddress((void**)&ap, g_attn);
    cudaGetSymbolAddress((void**)&xp, g_x);
    cudaGetSymbolAddress((void**)&wqkv, g_wqkv);
    cudaGetSymbolAddress((void**)&wop, g_wo);
    cudaGetSymbolAddress((void**)&ct, g_cos);
    cudaGetSymbolAddress((void**)&st, g_sin);

    size_t gsmem = (size_t)4 * GAB * sizeof(float);       // 73728 B
    size_t fsmem = (size_t)FWORDS * sizeof(uint32_t);     // 137216 B
    cudaFuncSetAttribute(gemm_tf32, cudaFuncAttributeMaxDynamicSharedMemorySize,
                         (int)gsmem);
    cudaFuncSetAttribute(gemm_qkv, cudaFuncAttributeMaxDynamicSharedMemorySize,
                         (int)gsmem);
    cudaFuncSetAttribute(flash_tf32, cudaFuncAttributeMaxDynamicSharedMemorySize,
                         (int)fsmem);

    rope_table_kernel<<<(SEQ_T * 64) / 256, 256>>>(ct, st);

    // pre-round inputs to tf32
    {
        int n4;
        n4 = (M_ROWS * DIM) / 4;
        rnd_kernel<<<(n4 + 255) / 256, 256>>>((const float4*)x, (float4*)xp, n4);
        n4 = (DIM * DIM) / 4;
        rnd_kernel<<<(n4 + 255) / 256, 256>>>((const float4*)wq, (float4*)wqkv, n4);
        n4 = (N_KVH * HEAD_DIM * DIM) / 4;
        rnd_kernel<<<(n4 + 255) / 256, 256>>>((const float4*)wk,
            (float4*)(wqkv + (size_t)DIM * DIM), n4);
        rnd_kernel<<<(n4 + 255) / 256, 256>>>((const float4*)wv,
            (float4*)(wqkv + (size_t)(DIM + N_KVH * HEAD_DIM) * DIM), n4);
        n4 = (DIM * DIM) / 4;
        rnd_kernel<<<(n4 + 255) / 256, 256>>>((const float4*)wo, (float4*)wop, n4);
    }

    // fused QKV projection
    gemm_qkv<<<dim3(NQKV / 128, M_ROWS / 128), 256, gsmem>>>(
        xp, wqkv, bk, bv, qp, kp, vp, DIM);

    const float qscale = 0.08838834764831845f;   // 1/sqrt(128)
    rope_kernel<<<((size_t)M_ROWS * N_HEAD * 64) / 256, 256>>>(qp, ct, st,
                                                               N_HEAD, qscale);
    rope_kernel<<<((size_t)M_ROWS * N_KVH * 64) / 256, 256>>>(kp, ct, st,
                                                              N_KVH, 1.0f);

    flash_tf32<<<dim3(SEQ_T / 128, N_HEAD, BATCH), 256, fsmem>>>(qp, kp, vp, ap);

    gemm_tf32<<<dim3(DIM / 128, M_ROWS / 128), 256, gsmem>>>(
        ap, wop, bo, out, DIM, DIM);
}

// round 7
// speedup vs baseline: 6.8849x; 1.9246x over previous
#include <cuda_runtime.h>
#include <cuda_fp16.h>
#include <math.h>
#include <stdint.h>

// ---------------------------------------------------------------------------
// GroupedQueryAttention — fp16 tensor-core v5
//  fp16 (10-bit mantissa == tf32) operands, fp32 accumulate, everywhere.
//  m16n8k16 -> half the mma instructions, half the smem bytes of tf32 path.
//  Flash: C-frag == A-frag layout for fp16 -> P feeds PV mma with NO shfl.
// ---------------------------------------------------------------------------

#define DIM      2048
#define HEAD_DIM 128
#define N_HEAD   16
#define N_KVH    4
#define SEQ_T    2048
#define BATCH    2
#define M_ROWS   (BATCH * SEQ_T)          // 4096
#define NQKV     (DIM + 2 * N_KVH * HEAD_DIM)   // 3072

__device__ float  g_q    [(size_t)M_ROWS * DIM];               // pre-rope q (f32)
__device__ float  g_k    [(size_t)M_ROWS * N_KVH * HEAD_DIM];  // pre-rope k (f32)
__device__ __half g_qh   [(size_t)M_ROWS * DIM];               // roped+scaled q
__device__ __half g_kh   [(size_t)M_ROWS * N_KVH * HEAD_DIM];
__device__ __half g_vh   [(size_t)M_ROWS * N_KVH * HEAD_DIM];
__device__ __half g_attnh[(size_t)M_ROWS * DIM];
__device__ __half g_xh   [(size_t)M_ROWS * DIM];
__device__ __half g_wqkvh[(size_t)NQKV * DIM];
__device__ __half g_woh  [(size_t)DIM * DIM];
__device__ float  g_cos  [SEQ_T * 64];
__device__ float  g_sin  [SEQ_T * 64];

// ------------------------------ helpers ------------------------------------
__device__ __forceinline__ uint32_t pkh2(float lo, float hi) {
    uint32_t u;
    asm("cvt.rn.f16x2.f32 %0, %1, %2;" : "=r"(u) : "f"(hi), "f"(lo));
    return u;
}
__device__ __forceinline__ void mma_f16(float c[4], const uint32_t a[4],
                                        uint32_t b0, uint32_t b1) {
    asm("mma.sync.aligned.m16n8k16.row.col.f32.f16.f16.f32 "
        "{%0,%1,%2,%3},{%4,%5,%6,%7},{%8,%9},{%0,%1,%2,%3};"
        : "+f"(c[0]), "+f"(c[1]), "+f"(c[2]), "+f"(c[3])
        : "r"(a[0]), "r"(a[1]), "r"(a[2]), "r"(a[3]), "r"(b0), "r"(b1));
}
__device__ __forceinline__ void ldsm_x4_t(uint32_t r[4], uint32_t addr) {
    asm volatile("ldmatrix.sync.aligned.m8n8.x4.trans.shared.b16 "
                 "{%0,%1,%2,%3}, [%4];"
                 : "=r"(r[0]), "=r"(r[1]), "=r"(r[2]), "=r"(r[3]) : "r"(addr));
}
__device__ __forceinline__ uint32_t smem_u32(const void* p) {
    uint32_t a;
    asm("{.reg .u64 t; cvta.to.shared.u64 t, %1; cvt.u32.u64 %0, t;}"
        : "=r"(a) : "l"(p));
    return a;
}
#define CPA16(dst, src) \
    asm volatile("cp.async.cg.shared.global [%0], [%1], 16;" :: "r"(dst), "l"(src))
#define CPCOMMIT() asm volatile("cp.async.commit_group;")
template <int N> __device__ __forceinline__ void cpwait() {
    asm volatile("cp.async.wait_group %0;" :: "n"(N));
}

// ------------------------- pre-round to fp16 --------------------------------
__global__ void rnd_h(const float4* __restrict__ src, uint2* __restrict__ dst,
                      int n4) {
    int i = blockIdx.x * blockDim.x + threadIdx.x;
    if (i < n4) {
        float4 v = src[i];
        uint2 o;
        o.x = pkh2(v.x, v.y);
        o.y = pkh2(v.z, v.w);
        dst[i] = o;
    }
}

// ------------------------- RoPE tables (double) ----------------------------
__global__ void rope_table_kernel(float* ctab, float* stab) {
    int idx = blockIdx.x * blockDim.x + threadIdx.x;
    int t = idx >> 6;
    int j = idx & 63;
    double theta = exp(-((double)(2 * j) / 128.0) * log(10000.0));
    double ang = (double)t * theta;
    ctab[idx] = (float)cos(ang);
    stab[idx] = (float)sin(ang);
}

// ---------------- RoPE apply: f32 in -> scaled fp16 out ---------------------
__global__ void rope_h(const float* __restrict__ X, __half* __restrict__ Xh,
                       const float* __restrict__ ctab,
                       const float* __restrict__ stab, int H, float scale) {
    int idx = blockIdx.x * blockDim.x + threadIdx.x;
    int j = idx & 63;
    int r = idx >> 6;
    int h = r % H;
    int r2 = r / H;
    int t = r2 % SEQ_T;
    int b = r2 / SEQ_T;
    size_t off = ((size_t)(b * SEQ_T + t) * H + h) * HEAD_DIM;
    float c = ctab[t * 64 + j];
    float s = stab[t * 64 + j];
    float x1 = X[off + j];
    float x2 = X[off + j + 64];
    Xh[off + j]      = __float2half_rn((x1 * c - x2 * s) * scale);
    Xh[off + j + 64] = __float2half_rn((x2 * c + x1 * s) * scale);
}

// --------------------------- fp16 GEMM core ---------------------------------
// C[M,N] = A[M,K] @ W[N,K]^T (+bias). 128x128 tile, BK=64, 256 thr,
// cp.async double buffer. Row stride 72 halfs (36 u32) -> conflict-free frags.
#define GSTH 72                 // halfs per smem row
#define GSTU 36                 // u32 per smem row
#define GABH (128 * GSTH)       // halfs per buffer (18432 B)

struct GemmOut {
    void* C; const float* bias; int ldn; int col0; int mode;  // 0=f32, 1=half
};

__device__ __forceinline__ void gemm_body(
    const __half* __restrict__ Ablk, const __half* __restrict__ Wblk,
    int K, int by, const GemmOut& out, __half* gsm) {
    int tid = threadIdx.x;
    int wid = tid >> 5, lane = tid & 31;
    int wm = wid & 3, wn = wid >> 2;
    int g = lane >> 2, t = lane & 3;
    uint32_t sbase = smem_u32(gsm);

    float acc[2][8][4];
#pragma unroll
    for (int i = 0; i < 2; i++)
#pragma unroll
        for (int j = 0; j < 8; j++)
#pragma unroll
            for (int u = 0; u < 4; u++) acc[i][j][u] = 0.f;

    int ntiles = K / 64;

    // prologue: tile 0 -> buffer 0   (per matrix: 128 rows x 8 chunks of 16B)
    {
        uint32_t ab = sbase, wb = sbase + 2u * GABH * 2u;
#pragma unroll
        for (int p = 0; p < 4; p++) {
            int idx = tid + 256 * p;
            int row = idx >> 3, ch = idx & 7;
            CPA16(ab + row * 144 + ch * 16, Ablk + (size_t)row * K + ch * 8);
            CPA16(wb + row * 144 + ch * 16, Wblk + (size_t)row * K + ch * 8);
        }
        CPCOMMIT();
    }

    for (int tt = 0; tt < ntiles; tt++) {
        if (tt + 1 < ntiles) {
            int buf = (tt + 1) & 1;
            int kt = (tt + 1) * 64;
            uint32_t ab = sbase + (uint32_t)buf * GABH * 2u;
            uint32_t wb = sbase + (uint32_t)(2 + buf) * GABH * 2u;
#pragma unroll
            for (int p = 0; p < 4; p++) {
                int idx = tid + 256 * p;
                int row = idx >> 3, ch = idx & 7;
                CPA16(ab + row * 144 + ch * 16,
                      Ablk + (size_t)row * K + kt + ch * 8);
                CPA16(wb + row * 144 + ch * 16,
                      Wblk + (size_t)row * K + kt + ch * 8);
            }
            CPCOMMIT();
            cpwait<1>();
        } else {
            cpwait<0>();
        }
        __syncthreads();

        const uint32_t* As = (const uint32_t*)(gsm + (size_t)(tt & 1) * GABH);
        const uint32_t* Ws = (const uint32_t*)(gsm + (size_t)(2 + (tt & 1)) * GABH);
#pragma unroll
        for (int ks = 0; ks < 4; ks++) {
            uint32_t a[2][4], b[8][2];
#pragma unroll
            for (int mf = 0; mf < 2; mf++) {
                int rb = wm * 32 + mf * 16;
                a[mf][0] = As[(rb + g) * GSTU + ks * 8 + t];
                a[mf][1] = As[(rb + g + 8) * GSTU + ks * 8 + t];
                a[mf][2] = As[(rb + g) * GSTU + ks * 8 + 4 + t];
                a[mf][3] = As[(rb + g + 8) * GSTU + ks * 8 + 4 + t];
            }
#pragma unroll
            for (int nf = 0; nf < 8; nf++) {
                int nb = wn * 64 + nf * 8;
                b[nf][0] = Ws[(nb + g) * GSTU + ks * 8 + t];
                b[nf][1] = Ws[(nb + g) * GSTU + ks * 8 + 4 + t];
            }
#pragma unroll
            for (int mf = 0; mf < 2; mf++)
#pragma unroll
                for (int nf = 0; nf < 8; nf++)
                    mma_f16(acc[mf][nf], a[mf], b[nf][0], b[nf][1]);
        }
        __syncthreads();
    }

    // epilogue
#pragma unroll
    for (int mf = 0; mf < 2; mf++) {
        int r0 = by * 128 + wm * 32 + mf * 16 + g;
#pragma unroll
        for (int nf = 0; nf < 8; nf++) {
            int col = out.col0 + wn * 64 + nf * 8 + 2 * t;
            float b0 = out.bias ? out.bias[col] : 0.f;
            float b1 = out.bias ? out.bias[col + 1] : 0.f;
            float v00 = acc[mf][nf][0] + b0, v01 = acc[mf][nf][1] + b1;
            float v10 = acc[mf][nf][2] + b0, v11 = acc[mf][nf][3] + b1;
            if (out.mode == 0) {
                float* C = (float*)out.C;
                float2 w0 = {v00, v01}, w1 = {v10, v11};
                *(float2*)(C + (size_t)r0 * out.ldn + col) = w0;
                *(float2*)(C + (size_t)(r0 + 8) * out.ldn + col) = w1;
            } else {
                __half* C = (__half*)out.C;
                *(uint32_t*)(C + (size_t)r0 * out.ldn + col) = pkh2(v00, v01);
                *(uint32_t*)(C + (size_t)(r0 + 8) * out.ldn + col) = pkh2(v10, v11);
            }
        }
    }
}

// out-projection: half A/W -> f32 C (+bias)
__global__ void __launch_bounds__(256, 2)
gemm_h(const __half* __restrict__ A, const __half* __restrict__ W,
       const float* __restrict__ bias, float* __restrict__ C, int N, int K) {
    extern __shared__ __half gsm[];
    GemmOut out = {C, bias, N, (int)blockIdx.x * 128, 0};
    gemm_body(A + (size_t)blockIdx.y * 128 * K,
              W + (size_t)blockIdx.x * 128 * K, K, blockIdx.y, out, gsm);
}

// fused QKV: bx 0..15 -> q(f32); 16..19 -> k(f32,+bk); 20..23 -> v(half,+bv)
__global__ void __launch_bounds__(256, 2)
gemm_qkv(const __half* __restrict__ A, const __half* __restrict__ Wqkv,
         const float* __restrict__ bk, const float* __restrict__ bv,
         float* __restrict__ Q, float* __restrict__ Kt,
         __half* __restrict__ Vt, int K) {
    extern __shared__ __half gsm[];
    int bx = blockIdx.x;
    GemmOut out;
    if (bx < 16)      out = {Q,  nullptr, DIM, bx * 128, 0};
    else if (bx < 20) out = {Kt, bk, N_KVH * HEAD_DIM, (bx - 16) * 128, 0};
    else              out = {Vt, bv, N_KVH * HEAD_DIM, (bx - 20) * 128, 1};
    gemm_body(A + (size_t)blockIdx.y * 128 * K,
              Wqkv + (size_t)bx * 128 * K, K, blockIdx.y, out, gsm);
}

// ----------------------- fp16 flash attention -------------------------------
// 256 thr / 8 warps. BM=128, BN=64, cp.async double-buffered K/V (half),
// Q frags in regs, V via ldmatrix.x4.trans, P reuses C-frag layout (no shfl).
#define KSTH 136                 // halfs per K/V smem row (272 B)
#define KSTU 68
#define FK0 0
#define FK1 (64 * KSTU)
#define FV0 (2 * 64 * KSTU)
#define FV1 (FV0 + 64 * KSTU)
#define FWORDS (FV1 + 64 * KSTU)   // 17408 u32 = 69632 B

__global__ void __launch_bounds__(256, 1)
flash_h(const __half* __restrict__ Q, const __half* __restrict__ K,
        const __half* __restrict__ V, __half* __restrict__ O) {
    extern __shared__ uint32_t fsm[];
    int tid = threadIdx.x;
    int wid = tid >> 5, lane = tid & 31;
    int g = lane >> 2, t = lane & 3;
    int qt = gridDim.x - 1 - blockIdx.x;   // heavy blocks first
    int h  = blockIdx.y;
    int b  = blockIdx.z;
    int kvh = h >> 2;
    int q0 = qt * 128;
    int ntiles = 2 * qt + 2;

    uint32_t sb = smem_u32(fsm);
    uint32_t kbB[2] = {sb + FK0 * 4u, sb + FK1 * 4u};
    uint32_t vbB[2] = {sb + FV0 * 4u, sb + FV1 * 4u};

    // ldmatrix per-lane address components
    int vrow = (lane & 7) | (((lane >> 3) & 1) << 3);   // k offset 0..15
    int vcol = (lane >> 4) * 8;                          // n offset 0 or 8

    // ---- prologue: K/V tile 0 -> buffer 0 (64 rows x 16 chunks of 16B) ----
    {
#pragma unroll
        for (int p = 0; p < 4; p++) {
            int idx = tid + 256 * p;
            int row = idx >> 4, ch = idx & 15;
            size_t gb = ((size_t)(b * SEQ_T + row) * N_KVH + kvh) * HEAD_DIM + ch * 8;
            CPA16(kbB[0] + (row * KSTU + ch * 4) * 4, K + gb);
            CPA16(vbB[0] + (row * KSTU + ch * 4) * 4, V + gb);
        }
        CPCOMMIT();
    }

    // ---- stage Q tile (half) into buffer 1 region ----
#pragma unroll
    for (int p = 0; p < 8; p++) {
        int idx = tid + 256 * p;
        int row = idx >> 4, ch = idx & 15;
        const uint4 v = *(const uint4*)(Q +
            ((size_t)(b * SEQ_T + q0 + row) * N_HEAD + h) * HEAD_DIM + ch * 8);
        uint32_t* dst = (row < 64)
            ? (fsm + FK1 + row * KSTU + ch * 4)
            : (fsm + FV1 + (row - 64) * KSTU + ch * 4);
        *(uint4*)dst = v;
    }
    __syncthreads();

    // ---- Q fragments to registers (8 ksteps x 4 regs) ----
    uint32_t qf[8][4];
    {
        const uint32_t* qs;
        int r0;
        if (wid < 4) { qs = fsm + FK1; r0 = wid * 16; }
        else         { qs = fsm + FV1; r0 = (wid - 4) * 16; }
#pragma unroll
        for (int ks = 0; ks < 8; ks++) {
            qf[ks][0] = qs[(r0 + g) * KSTU + ks * 8 + t];
            qf[ks][1] = qs[(r0 + g + 8) * KSTU + ks * 8 + t];
            qf[ks][2] = qs[(r0 + g) * KSTU + ks * 8 + 4 + t];
            qf[ks][3] = qs[(r0 + g + 8) * KSTU + ks * 8 + 4 + t];
        }
    }
    __syncthreads();   // qf reads done before loop overwrites buffer 1

    float o[16][4];
#pragma unroll
    for (int nf = 0; nf < 16; nf++)
#pragma unroll
        for (int u = 0; u < 4; u++) o[nf][u] = 0.f;
    float m0 = -INFINITY, m1 = -INFINITY, l0 = 0.f, l1 = 0.f;

    int qrow0 = q0 + wid * 16 + g;

    for (int kt = 0; kt < ntiles; kt++) {
        if (kt + 1 < ntiles) {
            int buf = (kt + 1) & 1;
            int k0n = (kt + 1) * 64;
#pragma unroll
            for (int p = 0; p < 4; p++) {
                int idx = tid + 256 * p;
                int row = idx >> 4, ch = idx & 15;
                size_t gb = ((size_t)(b * SEQ_T + k0n + row) * N_KVH + kvh)
                            * HEAD_DIM + ch * 8;
                CPA16(kbB[buf] + (row * KSTU + ch * 4) * 4, K + gb);
                CPA16(vbB[buf] + (row * KSTU + ch * 4) * 4, V + gb);
            }
            CPCOMMIT();
            cpwait<1>();
        } else {
            cpwait<0>();
        }
        __syncthreads();

        const uint32_t* Ks = fsm + ((kt & 1) ? FK1 : FK0);
        uint32_t vbase = (kt & 1) ? vbB[1] : vbB[0];
        int k0 = kt * 64;

        // ---- S = Q @ K^T (8 ksteps of k16) ----
        float s[8][4];
#pragma unroll
        for (int nf = 0; nf < 8; nf++)
#pragma unroll
            for (int u = 0; u < 4; u++) s[nf][u] = 0.f;

#pragma unroll
        for (int ks = 0; ks < 8; ks++) {
            uint32_t bfr[8][2];
#pragma unroll
            for (int nf = 0; nf < 8; nf++) {
                bfr[nf][0] = Ks[(nf * 8 + g) * KSTU + ks * 8 + t];
                bfr[nf][1] = Ks[(nf * 8 + g) * KSTU + ks * 8 + 4 + t];
            }
#pragma unroll
            for (int nf = 0; nf < 8; nf++)
                mma_f16(s[nf], qf[ks], bfr[nf][0], bfr[nf][1]);
        }

        // ---- causal mask (only tiles straddling the diagonal) ----
        if (k0 + 63 > qrow0) {
            int r0 = qrow0, r1 = qrow0 + 8;
#pragma unroll
            for (int nf = 0; nf < 8; nf++) {
                int c0 = k0 + nf * 8 + 2 * t;
                if (c0 > r0)     s[nf][0] = -INFINITY;
                if (c0 + 1 > r0) s[nf][1] = -INFINITY;
                if (c0 > r1)     s[nf][2] = -INFINITY;
                if (c0 + 1 > r1) s[nf][3] = -INFINITY;
            }
        }

        // ---- online softmax ----
        float rm0 = -INFINITY, rm1 = -INFINITY;
#pragma unroll
        for (int nf = 0; nf < 8; nf++) {
            rm0 = fmaxf(rm0, fmaxf(s[nf][0], s[nf][1]));
            rm1 = fmaxf(rm1, fmaxf(s[nf][2], s[nf][3]));
        }
        rm0 = fmaxf(rm0, __shfl_xor_sync(0xffffffffu, rm0, 1));
        rm0 = fmaxf(rm0, __shfl_xor_sync(0xffffffffu, rm0, 2));
        rm1 = fmaxf(rm1, __shfl_xor_sync(0xffffffffu, rm1, 1));
        rm1 = fmaxf(rm1, __shfl_xor_sync(0xffffffffu, rm1, 2));
        float mn0 = fmaxf(m0, rm0), mn1 = fmaxf(m1, rm1);
        float f0 = __expf(m0 - mn0), f1 = __expf(m1 - mn1);
        m0 = mn0; m1 = mn1;

        float rs0 = 0.f, rs1 = 0.f;
#pragma unroll
        for (int nf = 0; nf < 8; nf++) {
            s[nf][0] = __expf(s[nf][0] - mn0);
            s[nf][1] = __expf(s[nf][1] - mn0);
            s[nf][2] = __expf(s[nf][2] - mn1);
            s[nf][3] = __expf(s[nf][3] - mn1);
            rs0 += s[nf][0] + s[nf][1];
            rs1 += s[nf][2] + s[nf][3];
        }
        rs0 += __shfl_xor_sync(0xffffffffu, rs0, 1);
        rs0 += __shfl_xor_sync(0xffffffffu, rs0, 2);
        rs1 += __shfl_xor_sync(0xffffffffu, rs1, 1);
        rs1 += __shfl_xor_sync(0xffffffffu, rs1, 2);
        l0 = l0 * f0 + rs0;
        l1 = l1 * f1 + rs1;
#pragma unroll
        for (int nf = 0; nf < 16; nf++) {
            o[nf][0] *= f0; o[nf][1] *= f0;
            o[nf][2] *= f1; o[nf][3] *= f1;
        }

        // ---- O += P @ V ; fp16 C-frag == A-frag layout, no shfl ----
#pragma unroll
        for (int ks2 = 0; ks2 < 4; ks2++) {
            uint32_t a[4];
            a[0] = pkh2(s[2 * ks2][0],     s[2 * ks2][1]);
            a[1] = pkh2(s[2 * ks2][2],     s[2 * ks2][3]);
            a[2] = pkh2(s[2 * ks2 + 1][0], s[2 * ks2 + 1][1]);
            a[3] = pkh2(s[2 * ks2 + 1][2], s[2 * ks2 + 1][3]);
#pragma unroll
            for (int nf2 = 0; nf2 < 8; nf2++) {
                uint32_t r[4];
                uint32_t addr = vbase +
                    ((ks2 * 16 + vrow) * KSTH + nf2 * 16 + vcol) * 2;
                ldsm_x4_t(r, addr);
                mma_f16(o[2 * nf2],     a, r[0], r[1]);
                mma_f16(o[2 * nf2 + 1], a, r[2], r[3]);
            }
        }
        __syncthreads();   // buffer reads done before next prefetch overwrites
    }

    // ---- epilogue: normalize, write half ----
    float inv0 = 1.f / l0, inv1 = 1.f / l1;
#pragma unroll
    for (int nf = 0; nf < 16; nf++) {
        int col = nf * 8 + 2 * t;
        __half* d0 = O + ((size_t)(b * SEQ_T + qrow0) * N_HEAD + h) * HEAD_DIM + col;
        __half* d1 = O + ((size_t)(b * SEQ_T + qrow0 + 8) * N_HEAD + h) * HEAD_DIM + col;
        *(uint32_t*)d0 = pkh2(o[nf][0] * inv0, o[nf][1] * inv0);
        *(uint32_t*)d1 = pkh2(o[nf][2] * inv1, o[nf][3] * inv1);
    }
}

// ------------------------------- launch ------------------------------------
extern "C" void kernel_launch(void* const* d_in, const int* in_sizes, int n_in,
                              void* d_out, int out_size) {
    const float* x  = (const float*)d_in[0];
    const float* wq = (const float*)d_in[1];
    const float* wk = (const float*)d_in[2];
    const float* bk = (const float*)d_in[3];
    const float* wv = (const float*)d_in[4];
    const float* bv = (const float*)d_in[5];
    const float* wo = (const float*)d_in[6];
    const float* bo = (const float*)d_in[7];
    float* out = (float*)d_out;

    float *qp, *kp, *ct, *st;
    __half *qh, *kh, *vh, *ah, *xh, *wqkvh, *woh;
    cudaGetSymbolAddress((void**)&qp, g_q);
    cudaGetSymbolAddress((void**)&kp, g_k);
    cudaGetSymbolAddress((void**)&qh, g_qh);
    cudaGetSymbolAddress((void**)&kh, g_kh);
    cudaGetSymbolAddress((void**)&vh, g_vh);
    cudaGetSymbolAddress((void**)&ah, g_attnh);
    cudaGetSymbolAddress((void**)&xh, g_xh);
    cudaGetSymbolAddress((void**)&wqkvh, g_wqkvh);
    cudaGetSymbolAddress((void**)&woh, g_woh);
    cudaGetSymbolAddress((void**)&ct, g_cos);
    cudaGetSymbolAddress((void**)&st, g_sin);

    size_t gsmem = (size_t)4 * GABH * sizeof(__half);     // 73728 B
    size_t fsmem = (size_t)FWORDS * sizeof(uint32_t);     // 69632 B
    cudaFuncSetAttribute(gemm_h, cudaFuncAttributeMaxDynamicSharedMemorySize,
                         (int)gsmem);
    cudaFuncSetAttribute(gemm_qkv, cudaFuncAttributeMaxDynamicSharedMemorySize,
                         (int)gsmem);
    cudaFuncSetAttribute(flash_h, cudaFuncAttributeMaxDynamicSharedMemorySize,
                         (int)fsmem);

    rope_table_kernel<<<(SEQ_T * 64) / 256, 256>>>(ct, st);

    // pre-round inputs to fp16
    {
        int n4;
        n4 = (M_ROWS * DIM) / 4;
        rnd_h<<<(n4 + 255) / 256, 256>>>((const float4*)x, (uint2*)xh, n4);
        n4 = (DIM * DIM) / 4;
        rnd_h<<<(n4 + 255) / 256, 256>>>((const float4*)wq, (uint2*)wqkvh, n4);
        n4 = (N_KVH * HEAD_DIM * DIM) / 4;
        rnd_h<<<(n4 + 255) / 256, 256>>>((const float4*)wk,
            (uint2*)(wqkvh + (size_t)DIM * DIM), n4);
        rnd_h<<<(n4 + 255) / 256, 256>>>((const float4*)wv,
            (uint2*)(wqkvh + (size_t)(DIM + N_KVH * HEAD_DIM) * DIM), n4);
        n4 = (DIM * DIM) / 4;
        rnd_h<<<(n4 + 255) / 256, 256>>>((const float4*)wo, (uint2*)woh, n4);
    }

    // fused QKV projection
    gemm_qkv<<<dim3(NQKV / 128, M_ROWS / 128), 256, gsmem>>>(
        xh, wqkvh, bk, bv, qp, kp, vh, DIM);

    const float qscale = 0.08838834764831845f;   // 1/sqrt(128)
    rope_h<<<((size_t)M_ROWS * N_HEAD * 64) / 256, 256>>>(qp, qh, ct, st,
                                                          N_HEAD, qscale);
    rope_h<<<((size_t)M_ROWS * N_KVH * 64) / 256, 256>>>(kp, kh, ct, st,
                                                         N_KVH, 1.0f);

    flash_h<<<dim3(SEQ_T / 128, N_HEAD, BATCH), 256, fsmem>>>(qh, kh, vh, ah);

    gemm_h<<<dim3(DIM / 128, M_ROWS / 128), 256, gsmem>>>(
        ah, woh, bo, out, DIM, DIM);
}